// round 3
// baseline (speedup 1.0000x reference)
#include <cuda_runtime.h>
#include <cuda_bf16.h>
#include <cstdint>

#define NN 10000
#define EE 160000
#define TEN 65536
#define EA (EE + NN)   // edges + self loops = 170000

// ---------------- scratch (static device globals; no allocation) ----------------
__device__ float g_w1c[384 * 384];    // fc1_w @ gat1_w
__device__ float g_b1c[384];          // fc1_b @ gat1_w
__device__ float g_h1[NN * 384];      // gat1 h = x @ w1c + b1c
__device__ float g_num1[NN * 384];    // gat1 unnormalized aggregate
__device__ float g_hr1[NN * 384];     // relu(x + bn1)
__device__ float g_h5[NN * 256];      // fc5 out
__device__ float g_h2[NN * 256];      // gat2 h
__device__ float g_num2[NN * 256];
__device__ float g_hr2[NN * 256];     // relu(h5 + bn2)
__device__ float g_hf[NN * 256];      // fc2 out

__device__ float g_as1[NN * 8], g_ad1[NN * 8], g_dn1[NN * 8];   // dn -> 1/den after invk
__device__ float g_as2[NN], g_ad2[NN], g_dn2[NN];
__device__ float g_sum1[384], g_ss1[384], g_mu1[384], g_rs1[384];
__device__ float g_sum2[256], g_ss2[256], g_mu2[256], g_rs2[256];

// ---------------- helpers ----------------
__device__ __forceinline__ void edge_sd(const int* __restrict__ ei, int e, int& s, int& d) {
    if (e < EE) { s = ei[e]; d = ei[EE + e]; }
    else        { s = e - EE; d = e - EE; }
}

__device__ __forceinline__ float leaky(float v) { return v > 0.f ? v : 0.2f * v; }

__device__ __forceinline__ uint32_t prmt(uint32_t a, uint32_t b, uint32_t c) {
    uint32_t d;
    asm("prmt.b32 %0, %1, %2, %3;" : "=r"(d) : "r"(a), "r"(b), "r"(c));
    return d;
}

// pack float into (bf16_lo << 16) | bf16_hi where hi+lo ~= v (17-bit mantissa)
__device__ __forceinline__ uint32_t pack_hl(float v) {
    __nv_bfloat16 bh = __float2bfloat16(v);
    float fh = __bfloat162float(bh);
    __nv_bfloat16 bl = __float2bfloat16(v - fh);
    return ((uint32_t)__bfloat16_as_ushort(bl) << 16) | (uint32_t)__bfloat16_as_ushort(bh);
}

// ---------------- bf16x2-split tensor GEMM: C = A @ B (+bias) -----------------
// 128x128 block, BK=32, 256 threads (8 warps 2x4), warp tile 64x32.
// Per k16-step and logical 16x8 tile: 3 MMAs (ah*bh + ah*bl + al*bh).
// Requires K%32==0, Nc%128==0. M tail guarded.
#define KP 33
__global__ void __launch_bounds__(256) gemm_bfx(
    const float* __restrict__ A, const float* __restrict__ B,
    const float* __restrict__ bias, float* __restrict__ C,
    int M, int K, int Nc)
{
    __shared__ uint32_t As[128 * KP];   // [m][k] packed hi/lo
    __shared__ uint32_t Bs[128 * KP];   // [n][k] packed hi/lo (transposed)
    const int t = threadIdx.x, lane = t & 31, wid = t >> 5;
    const int wm = (wid & 1) * 64, wn = (wid >> 1) * 32;
    const int m0 = blockIdx.y * 128, n0 = blockIdx.x * 128;
    float acc[4][4][4];
#pragma unroll
    for (int i = 0; i < 4; i++)
#pragma unroll
        for (int j = 0; j < 4; j++)
#pragma unroll
            for (int q = 0; q < 4; q++) acc[i][j][q] = 0.f;

    for (int k0 = 0; k0 < K; k0 += 32) {
        // stage A (float4 coalesced; conflict-free STS: (m+k)%32 bijective)
#pragma unroll
        for (int j = 0; j < 4; j++) {
            int idx = t + 256 * j;
            int row = idx >> 3, kc = (idx & 7) * 4;
            float4 v = make_float4(0.f, 0.f, 0.f, 0.f);
            if (m0 + row < M)
                v = *(const float4*)&A[(size_t)(m0 + row) * K + k0 + kc];
            As[row * KP + kc + 0] = pack_hl(v.x);
            As[row * KP + kc + 1] = pack_hl(v.y);
            As[row * KP + kc + 2] = pack_hl(v.z);
            As[row * KP + kc + 3] = pack_hl(v.w);
        }
        // stage B transposed (scalar coalesced reads; conflict-free STS)
#pragma unroll
        for (int j = 0; j < 16; j++) {
            int idx = t + 256 * j;
            int kr = idx >> 7, n = idx & 127;
            float v = B[(size_t)(k0 + kr) * Nc + n0 + n];
            Bs[n * KP + kr] = pack_hl(v);
        }
        __syncthreads();
#pragma unroll
        for (int ks = 0; ks < 2; ks++) {
            const int kb = ks * 16 + 2 * (lane & 3);
            // B fragments for all 4 nt
            uint32_t bh[4][2], bl[4][2];
#pragma unroll
            for (int nt = 0; nt < 4; nt++) {
                int n = wn + nt * 8 + (lane >> 2);
                uint32_t v0 = Bs[n * KP + kb], v1 = Bs[n * KP + kb + 1];
                uint32_t v2 = Bs[n * KP + kb + 8], v3 = Bs[n * KP + kb + 9];
                bh[nt][0] = prmt(v0, v1, 0x5410); bl[nt][0] = prmt(v0, v1, 0x7632);
                bh[nt][1] = prmt(v2, v3, 0x5410); bl[nt][1] = prmt(v2, v3, 0x7632);
            }
#pragma unroll
            for (int mt = 0; mt < 4; mt++) {
                int m = wm + mt * 16 + (lane >> 2);
                const uint32_t* r0 = &As[m * KP + kb];
                const uint32_t* r1 = &As[(m + 8) * KP + kb];
                uint32_t u0 = r0[0], u1 = r0[1], u2 = r1[0], u3 = r1[1];
                uint32_t u4 = r0[8], u5 = r0[9], u6 = r1[8], u7 = r1[9];
                uint32_t ah[4], al[4];
                ah[0] = prmt(u0, u1, 0x5410); al[0] = prmt(u0, u1, 0x7632);
                ah[1] = prmt(u2, u3, 0x5410); al[1] = prmt(u2, u3, 0x7632);
                ah[2] = prmt(u4, u5, 0x5410); al[2] = prmt(u4, u5, 0x7632);
                ah[3] = prmt(u6, u7, 0x5410); al[3] = prmt(u6, u7, 0x7632);
#pragma unroll
                for (int nt = 0; nt < 4; nt++) {
#define MMA_BF16(AV, BV)                                                      \
    asm volatile(                                                             \
        "mma.sync.aligned.m16n8k16.row.col.f32.bf16.bf16.f32 "                \
        "{%0,%1,%2,%3}, {%4,%5,%6,%7}, {%8,%9}, {%0,%1,%2,%3};\n"             \
        : "+f"(acc[mt][nt][0]), "+f"(acc[mt][nt][1]),                         \
          "+f"(acc[mt][nt][2]), "+f"(acc[mt][nt][3])                          \
        : "r"(AV[0]), "r"(AV[1]), "r"(AV[2]), "r"(AV[3]),                     \
          "r"(BV[0]), "r"(BV[1]))
                    MMA_BF16(ah, bh[nt]);
                    MMA_BF16(ah, bl[nt]);
                    MMA_BF16(al, bh[nt]);
#undef MMA_BF16
                }
            }
        }
        __syncthreads();
    }
    // epilogue
#pragma unroll
    for (int mt = 0; mt < 4; mt++) {
#pragma unroll
        for (int nt = 0; nt < 4; nt++) {
            int r = m0 + wm + mt * 16 + (lane >> 2);
            int c = n0 + wn + nt * 8 + 2 * (lane & 3);
            float b0 = bias ? bias[c] : 0.f;
            float b1 = bias ? bias[c + 1] : 0.f;
            if (r < M) {
                float2 v = make_float2(acc[mt][nt][0] + b0, acc[mt][nt][1] + b1);
                *(float2*)&C[(size_t)r * Nc + c] = v;
            }
            if (r + 8 < M) {
                float2 v = make_float2(acc[mt][nt][2] + b0, acc[mt][nt][3] + b1);
                *(float2*)&C[(size_t)(r + 8) * Nc + c] = v;
            }
        }
    }
}

// ---------------- fp32 split-K GEMM for the 384^3 weight fuse ------------------
// grid.z = K-chunks; accumulates with atomicAdd into pre-zeroed C.
__global__ void gemm64sk(const float* __restrict__ A, const float* __restrict__ B,
                         float* __restrict__ C, int M, int K, int Nc) {
    __shared__ float As[16][64];
    __shared__ float Bs[16][64];
    const int tx = threadIdx.x, ty = threadIdx.y;
    const int t = ty * 16 + tx;
    const int m0 = blockIdx.y * 64, n0 = blockIdx.x * 64;
    const int Kc = K / gridDim.z;
    const int kbeg = blockIdx.z * Kc, kend = kbeg + Kc;
    const int la_m = t >> 2, la_k = (t & 3) * 4;
    const int lb_k = t >> 4, lb_n = (t & 15) * 4;
    float acc[4][4] = {};
    for (int k0 = kbeg; k0 < kend; k0 += 16) {
        float4 av = *(const float4*)&A[(size_t)(m0 + la_m) * K + k0 + la_k];
        As[la_k + 0][la_m] = av.x; As[la_k + 1][la_m] = av.y;
        As[la_k + 2][la_m] = av.z; As[la_k + 3][la_m] = av.w;
        *(float4*)&Bs[lb_k][lb_n] =
            *(const float4*)&B[(size_t)(k0 + lb_k) * Nc + n0 + lb_n];
        __syncthreads();
#pragma unroll
        for (int kk = 0; kk < 16; kk++) {
            float4 a = *(const float4*)&As[kk][ty * 4];
            float4 b = *(const float4*)&Bs[kk][tx * 4];
            float ar[4] = {a.x, a.y, a.z, a.w};
            float br[4] = {b.x, b.y, b.z, b.w};
#pragma unroll
            for (int i = 0; i < 4; i++)
#pragma unroll
                for (int j = 0; j < 4; j++) acc[i][j] += ar[i] * br[j];
        }
        __syncthreads();
    }
#pragma unroll
    for (int i = 0; i < 4; i++)
#pragma unroll
        for (int j = 0; j < 4; j++)
            atomicAdd(&C[(size_t)(m0 + ty * 4 + i) * Nc + n0 + tx * 4 + j], acc[i][j]);
}

__global__ void zerow1c() {
    int i = blockIdx.x * blockDim.x + threadIdx.x;
    if (i < 384 * 384) g_w1c[i] = 0.f;
}

// b1c[j] = sum_k fc1_b[k] * gat1_w[k][j]
__global__ void biascomb(const float* __restrict__ fb, const float* __restrict__ W) {
    int j = blockIdx.x * blockDim.x + threadIdx.x;
    if (j >= 384) return;
    float s = 0.f;
    for (int k = 0; k < 384; k++) s += fb[k] * W[k * 384 + j];
    g_b1c[j] = s;
}

// ---------------- init ----------------
__global__ void init1k() {
    int idx = blockIdx.x * blockDim.x + threadIdx.x;
    if (idx < NN * 384) g_num1[idx] = 0.f;
    if (idx < NN * 8) g_dn1[idx] = 0.f;
    if (idx < 384) { g_sum1[idx] = 0.f; g_ss1[idx] = 0.f; }
}
__global__ void init2k() {
    int idx = blockIdx.x * blockDim.x + threadIdx.x;
    if (idx < NN * 256) g_num2[idx] = 0.f;
    if (idx < NN) g_dn2[idx] = 0.f;
    if (idx < 256) { g_sum2[idx] = 0.f; g_ss2[idx] = 0.f; }
}

// ---------------- GAT1 coefficients ----------------
__global__ void coef1k(const float* __restrict__ asw, const float* __restrict__ adw) {
    __shared__ float sacc[8][16];
    int t = threadIdx.x, lane = t & 31, w = t >> 5;
    int n = blockIdx.x * 8 + w;
    if (lane < 16) sacc[w][lane] = 0.f;
    __syncwarp();
    if (n < NN) {
        const float4* hp = (const float4*)(g_h1 + (size_t)n * 384);
        const float4* ap = (const float4*)asw;
        const float4* dp = (const float4*)adw;
#pragma unroll
        for (int i = 0; i < 3; i++) {
            int c4 = lane + 32 * i;
            int hd = c4 / 12;
            float4 v = hp[c4], a = ap[c4], dd = dp[c4];
            float s = v.x * a.x + v.y * a.y + v.z * a.z + v.w * a.w;
            float d2 = v.x * dd.x + v.y * dd.y + v.z * dd.z + v.w * dd.w;
            atomicAdd(&sacc[w][hd], s);
            atomicAdd(&sacc[w][8 + hd], d2);
        }
        __syncwarp();
        if (lane < 8)       g_as1[n * 8 + lane] = sacc[w][lane];
        else if (lane < 16) g_ad1[n * 8 + (lane - 8)] = sacc[w][lane];
    }
}

// ---------------- GAT1 single-pass scatter (vector atomics) -------------------
__global__ void scat1k(const int* __restrict__ ei) {
    int gw = (blockIdx.x * blockDim.x + threadIdx.x) >> 5;
    if (gw >= EA) return;
    int lane = threadIdx.x & 31;
    int s, d;
    edge_sd(ei, gw, s, d);
    float ex = 0.f;
    if (lane < 8) {
        float e = leaky(g_as1[s * 8 + lane] + g_ad1[d * 8 + lane]);
        ex = __expf(e);
        atomicAdd(&g_dn1[d * 8 + lane], ex);
    }
    const float4* hs = (const float4*)(g_h1 + (size_t)s * 384);
    float4* nd = (float4*)(g_num1 + (size_t)d * 384);
#pragma unroll
    for (int i = 0; i < 3; i++) {
        int c4 = lane + 32 * i;
        float a = __shfl_sync(0xffffffffu, ex, c4 / 12);
        float4 v = hs[c4];
        atomicAdd(&nd[c4], make_float4(v.x * a, v.y * a, v.z * a, v.w * a));
    }
}

// ---------------- GAT2 ----------------
__global__ void coef2k(const float* __restrict__ asw, const float* __restrict__ adw) {
    int gw = (blockIdx.x * blockDim.x + threadIdx.x) >> 5;
    if (gw >= NN) return;
    int lane = threadIdx.x & 31;
    const float* hp = g_h2 + (size_t)gw * 256;
    float s = 0.f, d = 0.f;
#pragma unroll
    for (int k = 0; k < 8; k++) {
        int c = lane + 32 * k;
        float v = hp[c];
        s += v * asw[c]; d += v * adw[c];
    }
#pragma unroll
    for (int off = 16; off; off >>= 1) {
        s += __shfl_down_sync(0xffffffffu, s, off);
        d += __shfl_down_sync(0xffffffffu, d, off);
    }
    if (lane == 0) { g_as2[gw] = s; g_ad2[gw] = d; }
}

__global__ void scat2k(const int* __restrict__ ei) {
    int gw = (blockIdx.x * blockDim.x + threadIdx.x) >> 5;
    if (gw >= EA) return;
    int lane = threadIdx.x & 31;
    int s, d;
    edge_sd(ei, gw, s, d);
    float ex = 0.f;
    if (lane == 0) {
        ex = __expf(leaky(g_as2[s] + g_ad2[d]));
        atomicAdd(&g_dn2[d], ex);
    }
    ex = __shfl_sync(0xffffffffu, ex, 0);
    const float4* hs = (const float4*)(g_h2 + (size_t)s * 256);
    float4* nd = (float4*)(g_num2 + (size_t)d * 256);
#pragma unroll
    for (int i = 0; i < 2; i++) {
        int c4 = lane + 32 * i;
        float4 v = hs[c4];
        atomicAdd(&nd[c4], make_float4(v.x * ex, v.y * ex, v.z * ex, v.w * ex));
    }
}

// den -> 1/(den+1e-16), in place
__global__ void inv1k() {
    int i = blockIdx.x * blockDim.x + threadIdx.x;
    if (i < NN * 8) g_dn1[i] = 1.f / (g_dn1[i] + 1e-16f);
}
__global__ void inv2k() {
    int i = blockIdx.x * blockDim.x + threadIdx.x;
    if (i < NN) g_dn2[i] = 1.f / (g_dn2[i] + 1e-16f);
}

// ---------------- batch norm ----------------
__global__ void bnp1() {
    int col = blockIdx.x * 32 + threadIdx.x;
    int hd = col / 48;
    float s = 0.f, q = 0.f;
    for (int r = threadIdx.y + blockIdx.y * 8; r < NN; r += 8 * gridDim.y) {
        float v = g_num1[(size_t)r * 384 + col] * g_dn1[r * 8 + hd];
        s += v; q += v * v;
    }
    __shared__ float sh[8][32], sh2[8][32];
    sh[threadIdx.y][threadIdx.x] = s;
    sh2[threadIdx.y][threadIdx.x] = q;
    __syncthreads();
    if (threadIdx.y == 0) {
#pragma unroll
        for (int y = 1; y < 8; y++) { s += sh[y][threadIdx.x]; q += sh2[y][threadIdx.x]; }
        atomicAdd(&g_sum1[col], s);
        atomicAdd(&g_ss1[col], q);
    }
}
__global__ void bnp2() {
    int col = blockIdx.x * 32 + threadIdx.x;
    float s = 0.f, q = 0.f;
    for (int r = threadIdx.y + blockIdx.y * 8; r < NN; r += 8 * gridDim.y) {
        float v = g_num2[(size_t)r * 256 + col] * g_dn2[r];
        s += v; q += v * v;
    }
    __shared__ float sh[8][32], sh2[8][32];
    sh[threadIdx.y][threadIdx.x] = s;
    sh2[threadIdx.y][threadIdx.x] = q;
    __syncthreads();
    if (threadIdx.y == 0) {
#pragma unroll
        for (int y = 1; y < 8; y++) { s += sh[y][threadIdx.x]; q += sh2[y][threadIdx.x]; }
        atomicAdd(&g_sum2[col], s);
        atomicAdd(&g_ss2[col], q);
    }
}

__global__ void bn_final(int C, const float* __restrict__ sum, const float* __restrict__ ss,
                         float* __restrict__ mu, float* __restrict__ rs) {
    int c = blockIdx.x * blockDim.x + threadIdx.x;
    if (c >= C) return;
    float m = sum[c] * (1.f / NN);
    float v = ss[c] * (1.f / NN) - m * m;
    mu[c] = m;
    rs[c] = rsqrtf(v + 1e-5f);
}

// hr = relu(residual + (num*invden - mu)*rstd*gamma + beta)
__global__ void fuse1k(const float* __restrict__ x,
                       const float* __restrict__ g, const float* __restrict__ b) {
    int idx = blockIdx.x * blockDim.x + threadIdx.x;
    if (idx >= NN * 384) return;
    int c = idx % 384;
    int r = idx / 384;
    float val = g_num1[idx] * g_dn1[r * 8 + c / 48];
    val = (val - g_mu1[c]) * g_rs1[c] * g[c] + b[c];
    float h = x[idx] + val;
    g_hr1[idx] = h > 0.f ? h : 0.f;
}
__global__ void fuse2k(const float* __restrict__ g, const float* __restrict__ b) {
    int idx = blockIdx.x * blockDim.x + threadIdx.x;
    if (idx >= NN * 256) return;
    int c = idx & 255;
    int r = idx >> 8;
    float val = g_num2[idx] * g_dn2[r];
    val = (val - g_mu2[c]) * g_rs2[c] * g[c] + b[c];
    float h = g_h5[idx] + val;
    g_hr2[idx] = h > 0.f ? h : 0.f;
}

// ---------------- pair head ----------------
__global__ void pairk(const int* __restrict__ ei, const int* __restrict__ tid,
                      const float* __restrict__ w4, const float* __restrict__ b4,
                      float* __restrict__ out) {
    int gw = (blockIdx.x * blockDim.x + threadIdx.x) >> 5;
    if (gw >= TEN) return;
    int lane = threadIdx.x & 31;
    int e = tid[gw];
    int s = ei[e], d = ei[EE + e];
    const float* hs = g_hf + (size_t)s * 256;
    const float* hd = g_hf + (size_t)d * 256;
    float acc[7] = {};
#pragma unroll
    for (int k = 0; k < 8; k++) {
        int c = lane + 32 * k;
        float p = hs[c] * hd[c];
        const float* wr = &w4[c * 7];
#pragma unroll
        for (int j = 0; j < 7; j++) acc[j] += p * wr[j];
    }
#pragma unroll
    for (int j = 0; j < 7; j++)
#pragma unroll
        for (int off = 16; off; off >>= 1)
            acc[j] += __shfl_down_sync(0xffffffffu, acc[j], off);
    if (lane == 0) {
#pragma unroll
        for (int j = 0; j < 7; j++) out[(size_t)gw * 7 + j] = acc[j] + b4[j];
    }
}

// ---------------- launch ----------------
extern "C" void kernel_launch(void* const* d_in, const int* in_sizes, int n_in,
                              void* d_out, int out_size) {
    const float* x       = (const float*)d_in[0];
    const int*   ei      = (const int*)d_in[1];
    const int*   teid    = (const int*)d_in[2];
    const float* fc1_w   = (const float*)d_in[3];
    const float* fc1_b   = (const float*)d_in[4];
    const float* fc5_w   = (const float*)d_in[5];
    const float* fc5_b   = (const float*)d_in[6];
    const float* fc2_w   = (const float*)d_in[7];
    const float* fc2_b   = (const float*)d_in[8];
    const float* fc4_w   = (const float*)d_in[9];
    const float* fc4_b   = (const float*)d_in[10];
    const float* gat1_w  = (const float*)d_in[11];
    const float* gat1_as = (const float*)d_in[12];
    const float* gat1_ad = (const float*)d_in[13];
    /* gat1_b unused: BN-invariant */
    const float* gat2_w  = (const float*)d_in[15];
    const float* gat2_as = (const float*)d_in[16];
    const float* gat2_ad = (const float*)d_in[17];
    /* gat2_b unused: BN-invariant */
    const float* bn1_g   = (const float*)d_in[19];
    const float* bn1_b   = (const float*)d_in[20];
    const float* bn2_g   = (const float*)d_in[21];
    const float* bn2_b   = (const float*)d_in[22];
    float* out = (float*)d_out;

    float *p_w1c, *p_b1c, *p_h1, *p_hr1, *p_h5, *p_h2, *p_hr2, *p_hf;
    float *p_sum1, *p_ss1, *p_mu1, *p_rs1, *p_sum2, *p_ss2, *p_mu2, *p_rs2;
    cudaGetSymbolAddress((void**)&p_w1c, g_w1c);
    cudaGetSymbolAddress((void**)&p_b1c, g_b1c);
    cudaGetSymbolAddress((void**)&p_h1, g_h1);
    cudaGetSymbolAddress((void**)&p_hr1, g_hr1);
    cudaGetSymbolAddress((void**)&p_h5, g_h5);
    cudaGetSymbolAddress((void**)&p_h2, g_h2);
    cudaGetSymbolAddress((void**)&p_hr2, g_hr2);
    cudaGetSymbolAddress((void**)&p_hf, g_hf);
    cudaGetSymbolAddress((void**)&p_sum1, g_sum1);
    cudaGetSymbolAddress((void**)&p_ss1, g_ss1);
    cudaGetSymbolAddress((void**)&p_mu1, g_mu1);
    cudaGetSymbolAddress((void**)&p_rs1, g_rs1);
    cudaGetSymbolAddress((void**)&p_sum2, g_sum2);
    cudaGetSymbolAddress((void**)&p_ss2, g_ss2);
    cudaGetSymbolAddress((void**)&p_mu2, g_mu2);
    cudaGetSymbolAddress((void**)&p_rs2, g_rs2);

    const int MB = (NN + 127) / 128;  // 79

    // weight fusion: w1c = fc1_w @ gat1_w (split-K fp32) ; b1c = fc1_b @ gat1_w
    zerow1c<<<(384 * 384 + 255) / 256, 256>>>();
    gemm64sk<<<dim3(6, 6, 4), dim3(16, 16)>>>(fc1_w, gat1_w, p_w1c, 384, 384, 384);
    biascomb<<<3, 128>>>(fc1_b, gat1_w);
    init1k<<<(NN * 384 + 255) / 256, 256>>>();

    // h1 = x @ w1c + b1c
    gemm_bfx<<<dim3(3, MB), 256>>>(x, p_w1c, p_b1c, p_h1, NN, 384, 384);

    coef1k<<<(NN + 7) / 8, 256>>>(gat1_as, gat1_ad);
    scat1k<<<(EA * 32 + 255) / 256, 256>>>(ei);
    inv1k<<<(NN * 8 + 255) / 256, 256>>>();

    bnp1<<<dim3(12, 16), dim3(32, 8)>>>();
    bn_final<<<2, 256>>>(384, p_sum1, p_ss1, p_mu1, p_rs1);
    fuse1k<<<(NN * 384 + 255) / 256, 256>>>(x, bn1_g, bn1_b);

    // h5 = hr1 @ fc5_w + fc5_b ; h2 = h5 @ gat2_w
    gemm_bfx<<<dim3(2, MB), 256>>>(p_hr1, fc5_w, fc5_b, p_h5, NN, 384, 256);
    init2k<<<(NN * 256 + 255) / 256, 256>>>();
    gemm_bfx<<<dim3(2, MB), 256>>>(p_h5, gat2_w, nullptr, p_h2, NN, 256, 256);

    coef2k<<<(NN * 32 + 255) / 256, 256>>>(gat2_as, gat2_ad);
    scat2k<<<(EA * 32 + 255) / 256, 256>>>(ei);
    inv2k<<<(NN + 255) / 256, 256>>>();

    bnp2<<<dim3(8, 16), dim3(32, 8)>>>();
    bn_final<<<1, 256>>>(256, p_sum2, p_ss2, p_mu2, p_rs2);
    fuse2k<<<(NN * 256 + 255) / 256, 256>>>(bn2_g, bn2_b);

    // hf = hr2 @ fc2_w + fc2_b
    gemm_bfx<<<dim3(2, MB), 256>>>(p_hr2, fc2_w, fc2_b, p_hf, NN, 256, 256);

    // pair head
    pairk<<<(TEN * 32 + 255) / 256, 256>>>(ei, teid, fc4_w, fc4_b, out);
}

// round 5
// speedup vs baseline: 1.8089x; 1.8089x over previous
#include <cuda_runtime.h>
#include <cuda_bf16.h>
#include <cstdint>

#define NN 10000
#define EE 160000
#define TEN 65536
#define EA (EE + NN)   // edges + self loops = 170000

// ---------------- scratch (static device globals; no allocation) ----------------
__device__ float g_w1c[384 * 384];    // fc1_w @ gat1_w
__device__ float g_b1c[384];          // fc1_b @ gat1_w
__device__ float g_h1[NN * 384];      // gat1 h = x @ w1c + b1c
__device__ float g_gout1[NN * 384];   // gat1 normalized aggregate
__device__ float g_hr1[NN * 384];     // relu(x + bn1)
__device__ float g_h5[NN * 256];      // fc5 out
__device__ float g_h2[NN * 256];      // gat2 h
__device__ float g_gout2[NN * 256];
__device__ float g_hr2[NN * 256];     // relu(h5 + bn2)
__device__ float g_hf[NN * 256];      // fc2 out

__device__ float g_as1[NN * 8], g_ad1[NN * 8];
__device__ float g_as2[NN], g_ad2[NN];
__device__ float g_psum1[16 * 384], g_pss1[16 * 384], g_mu1[384], g_rs1[384];
__device__ float g_psum2[16 * 256], g_pss2[16 * 256], g_mu2[256], g_rs2[256];

// CSR by destination (shared by both GAT layers)
__device__ int g_deg[NN];
__device__ int g_off[NN + 1];
__device__ int g_pos[NN];
__device__ int g_srcl[EA];

// ---------------- helpers ----------------
__device__ __forceinline__ void edge_sd(const int* __restrict__ ei, int e, int& s, int& d) {
    if (e < EE) { s = ei[e]; d = ei[EE + e]; }
    else        { s = e - EE; d = e - EE; }
}

__device__ __forceinline__ float leaky(float v) { return v > 0.f ? v : 0.2f * v; }

__device__ __forceinline__ uint32_t f2tf32(float v) {
    uint32_t u;
    asm("cvt.rna.tf32.f32 %0, %1;" : "=r"(u) : "f"(v));
    return u;
}

// ---------------- TF32 tensor-core GEMM (proven R2 version) -------------------
__global__ void __launch_bounds__(256) gemm_tf32(
    const float* __restrict__ A, const float* __restrict__ B,
    const float* __restrict__ bias, float* __restrict__ C,
    int M, int K, int Nc)
{
    __shared__ uint32_t As[128 * 36];
    __shared__ uint32_t Bs[32 * 136];
    const int t = threadIdx.x, lane = t & 31, wid = t >> 5;
    const int wm = (wid & 1) * 64, wn = (wid >> 1) * 32;
    const int m0 = blockIdx.y * 128, n0 = blockIdx.x * 128;
    float acc[4][4][4];
#pragma unroll
    for (int i = 0; i < 4; i++)
#pragma unroll
        for (int j = 0; j < 4; j++)
#pragma unroll
            for (int q = 0; q < 4; q++) acc[i][j][q] = 0.f;

    for (int k0 = 0; k0 < K; k0 += 32) {
#pragma unroll
        for (int j = 0; j < 4; j++) {
            int idx = t + 256 * j;
            int row = idx >> 3, kc = (idx & 7) * 4;
            float4 v = make_float4(0.f, 0.f, 0.f, 0.f);
            if (m0 + row < M)
                v = *(const float4*)&A[(size_t)(m0 + row) * K + k0 + kc];
            uint4 u = make_uint4(f2tf32(v.x), f2tf32(v.y), f2tf32(v.z), f2tf32(v.w));
            *(uint4*)&As[row * 36 + kc] = u;
        }
#pragma unroll
        for (int j = 0; j < 4; j++) {
            int idx = t + 256 * j;
            int kr = idx >> 5, nc = (idx & 31) * 4;
            float4 v = *(const float4*)&B[(size_t)(k0 + kr) * Nc + n0 + nc];
            uint4 u = make_uint4(f2tf32(v.x), f2tf32(v.y), f2tf32(v.z), f2tf32(v.w));
            *(uint4*)&Bs[kr * 136 + nc] = u;
        }
        __syncthreads();
#pragma unroll
        for (int ks = 0; ks < 4; ks++) {
            uint32_t af[4][4], bf[4][2];
            const int kk = ks * 8 + (lane & 3);
#pragma unroll
            for (int mt = 0; mt < 4; mt++) {
                int m = wm + mt * 16 + (lane >> 2);
                af[mt][0] = As[m * 36 + kk];
                af[mt][1] = As[(m + 8) * 36 + kk];
                af[mt][2] = As[m * 36 + kk + 4];
                af[mt][3] = As[(m + 8) * 36 + kk + 4];
            }
#pragma unroll
            for (int nt = 0; nt < 4; nt++) {
                int n = wn + nt * 8 + (lane >> 2);
                bf[nt][0] = Bs[kk * 136 + n];
                bf[nt][1] = Bs[(kk + 4) * 136 + n];
            }
#pragma unroll
            for (int mt = 0; mt < 4; mt++)
#pragma unroll
                for (int nt = 0; nt < 4; nt++) {
                    asm volatile(
                        "mma.sync.aligned.m16n8k8.row.col.f32.tf32.tf32.f32 "
                        "{%0,%1,%2,%3}, {%4,%5,%6,%7}, {%8,%9}, {%0,%1,%2,%3};\n"
                        : "+f"(acc[mt][nt][0]), "+f"(acc[mt][nt][1]),
                          "+f"(acc[mt][nt][2]), "+f"(acc[mt][nt][3])
                        : "r"(af[mt][0]), "r"(af[mt][1]), "r"(af[mt][2]), "r"(af[mt][3]),
                          "r"(bf[nt][0]), "r"(bf[nt][1]));
                }
        }
        __syncthreads();
    }
#pragma unroll
    for (int mt = 0; mt < 4; mt++) {
#pragma unroll
        for (int nt = 0; nt < 4; nt++) {
            int r = m0 + wm + mt * 16 + (lane >> 2);
            int c = n0 + wn + nt * 8 + 2 * (lane & 3);
            float b0 = bias ? bias[c] : 0.f;
            float b1 = bias ? bias[c + 1] : 0.f;
            if (r < M) {
                float2 v = make_float2(acc[mt][nt][0] + b0, acc[mt][nt][1] + b1);
                *(float2*)&C[(size_t)r * Nc + c] = v;
            }
            if (r + 8 < M) {
                float2 v = make_float2(acc[mt][nt][2] + b0, acc[mt][nt][3] + b1);
                *(float2*)&C[(size_t)(r + 8) * Nc + c] = v;
            }
        }
    }
}

// ---------------- fp32 split-K GEMM for the 384^3 weight fuse ------------------
__global__ void gemm64sk(const float* __restrict__ A, const float* __restrict__ B,
                         float* __restrict__ C, int M, int K, int Nc) {
    __shared__ float As[16][64];
    __shared__ float Bs[16][64];
    const int tx = threadIdx.x, ty = threadIdx.y;
    const int t = ty * 16 + tx;
    const int m0 = blockIdx.y * 64, n0 = blockIdx.x * 64;
    const int Kc = K / gridDim.z;
    const int kbeg = blockIdx.z * Kc, kend = kbeg + Kc;
    const int la_m = t >> 2, la_k = (t & 3) * 4;
    const int lb_k = t >> 4, lb_n = (t & 15) * 4;
    float acc[4][4] = {};
    for (int k0 = kbeg; k0 < kend; k0 += 16) {
        float4 av = *(const float4*)&A[(size_t)(m0 + la_m) * K + k0 + la_k];
        As[la_k + 0][la_m] = av.x; As[la_k + 1][la_m] = av.y;
        As[la_k + 2][la_m] = av.z; As[la_k + 3][la_m] = av.w;
        *(float4*)&Bs[lb_k][lb_n] =
            *(const float4*)&B[(size_t)(k0 + lb_k) * Nc + n0 + lb_n];
        __syncthreads();
#pragma unroll
        for (int kk = 0; kk < 16; kk++) {
            float4 a = *(const float4*)&As[kk][ty * 4];
            float4 b = *(const float4*)&Bs[kk][tx * 4];
            float ar[4] = {a.x, a.y, a.z, a.w};
            float br[4] = {b.x, b.y, b.z, b.w};
#pragma unroll
            for (int i = 0; i < 4; i++)
#pragma unroll
                for (int j = 0; j < 4; j++) acc[i][j] += ar[i] * br[j];
        }
        __syncthreads();
    }
#pragma unroll
    for (int i = 0; i < 4; i++)
#pragma unroll
        for (int j = 0; j < 4; j++)
            atomicAdd(&C[(size_t)(m0 + ty * 4 + i) * Nc + n0 + tx * 4 + j], acc[i][j]);
}

// zero w1c + degree counters
__global__ void zerok() {
    int i = blockIdx.x * blockDim.x + threadIdx.x;
    if (i < 384 * 384) g_w1c[i] = 0.f;
    if (i < NN) g_deg[i] = 0;
}

// b1c[j] = sum_k fc1_b[k] * gat1_w[k][j]
__global__ void biascomb(const float* __restrict__ fb, const float* __restrict__ W) {
    int j = blockIdx.x * blockDim.x + threadIdx.x;
    if (j >= 384) return;
    float s = 0.f;
    for (int k = 0; k < 384; k++) s += fb[k] * W[k * 384 + j];
    g_b1c[j] = s;
}

// ---------------- CSR build ----------------
__global__ void degk(const int* __restrict__ ei) {
    int e = blockIdx.x * blockDim.x + threadIdx.x;
    if (e >= EA) return;
    int s, d;
    edge_sd(ei, e, s, d);
    atomicAdd(&g_deg[d], 1);
}

// single-block exclusive scan of g_deg -> g_off; zeros g_pos
__global__ void __launch_bounds__(1024) scank() {
    __shared__ int sums[1024];
    const int t = threadIdx.x;
    const int CH = (NN + 1023) / 1024;   // 10
    int vals[(NN + 1023) / 1024];
    int base = t * CH;
    int local = 0;
#pragma unroll
    for (int i = 0; i < CH; i++) {
        int idx = base + i;
        int v = (idx < NN) ? g_deg[idx] : 0;
        vals[i] = v;
        local += v;
    }
    sums[t] = local;
    __syncthreads();
    for (int off = 1; off < 1024; off <<= 1) {
        int v = (t >= off) ? sums[t - off] : 0;
        __syncthreads();
        sums[t] += v;
        __syncthreads();
    }
    int prefix = (t == 0) ? 0 : sums[t - 1];
#pragma unroll
    for (int i = 0; i < CH; i++) {
        int idx = base + i;
        if (idx < NN) { g_off[idx] = prefix; prefix += vals[i]; }
    }
    if (t == 1023) g_off[NN] = prefix;
    for (int i = t; i < NN; i += 1024) g_pos[i] = 0;
}

__global__ void fillk(const int* __restrict__ ei) {
    int e = blockIdx.x * blockDim.x + threadIdx.x;
    if (e >= EA) return;
    int s, d;
    edge_sd(ei, e, s, d);
    int slot = atomicAdd(&g_pos[d], 1);
    g_srcl[g_off[d] + slot] = s;
}

// ---------------- GAT coefficients ----------------
__global__ void coef1k(const float* __restrict__ asw, const float* __restrict__ adw) {
    __shared__ float sacc[8][16];
    int t = threadIdx.x, lane = t & 31, w = t >> 5;
    int n = blockIdx.x * 8 + w;
    if (lane < 16) sacc[w][lane] = 0.f;
    __syncwarp();
    if (n < NN) {
        const float4* hp = (const float4*)(g_h1 + (size_t)n * 384);
        const float4* ap = (const float4*)asw;
        const float4* dp = (const float4*)adw;
#pragma unroll
        for (int i = 0; i < 3; i++) {
            int c4 = lane + 32 * i;
            int hd = c4 / 12;
            float4 v = hp[c4], a = ap[c4], dd = dp[c4];
            float s = v.x * a.x + v.y * a.y + v.z * a.z + v.w * a.w;
            float d2 = v.x * dd.x + v.y * dd.y + v.z * dd.z + v.w * dd.w;
            atomicAdd(&sacc[w][hd], s);
            atomicAdd(&sacc[w][8 + hd], d2);
        }
        __syncwarp();
        if (lane < 8)       g_as1[n * 8 + lane] = sacc[w][lane];
        else if (lane < 16) g_ad1[n * 8 + (lane - 8)] = sacc[w][lane];
    }
}

__global__ void coef2k(const float* __restrict__ asw, const float* __restrict__ adw) {
    int gw = (blockIdx.x * blockDim.x + threadIdx.x) >> 5;
    if (gw >= NN) return;
    int lane = threadIdx.x & 31;
    const float* hp = g_h2 + (size_t)gw * 256;
    float s = 0.f, d = 0.f;
#pragma unroll
    for (int k = 0; k < 8; k++) {
        int c = lane + 32 * k;
        float v = hp[c];
        s += v * asw[c]; d += v * adw[c];
    }
#pragma unroll
    for (int off = 16; off; off >>= 1) {
        s += __shfl_down_sync(0xffffffffu, s, off);
        d += __shfl_down_sync(0xffffffffu, d, off);
    }
    if (lane == 0) { g_as2[gw] = s; g_ad2[gw] = d; }
}

// ---------------- CSR gather aggregation (no atomics, normalized output) ------
__global__ void gath1k() {
    int w = (blockIdx.x * blockDim.x + threadIdx.x) >> 5;
    if (w >= NN) return;
    int lane = threadIdx.x & 31;
    int beg = g_off[w], end = g_off[w + 1];   // end > beg (self-loop guarantees)
    float ad = (lane < 8) ? g_ad1[w * 8 + lane] : 0.f;
    float den = 0.f;
    float4 acc[3];
#pragma unroll
    for (int i = 0; i < 3; i++) acc[i] = make_float4(0.f, 0.f, 0.f, 0.f);

    int s = g_srcl[beg];
    for (int j = beg; j < end; j++) {
        int snext = (j + 1 < end) ? g_srcl[j + 1] : 0;
        float ex = 0.f;
        if (lane < 8) {
            ex = __expf(leaky(g_as1[s * 8 + lane] + ad));
            den += ex;
        }
        const float4* hs = (const float4*)(g_h1 + (size_t)s * 384);
#pragma unroll
        for (int i = 0; i < 3; i++) {
            int c4 = lane + 32 * i;
            float a = __shfl_sync(0xffffffffu, ex, c4 / 12);
            float4 v = hs[c4];
            acc[i].x += v.x * a; acc[i].y += v.y * a;
            acc[i].z += v.z * a; acc[i].w += v.w * a;
        }
        s = snext;
    }
    float4* od = (float4*)(g_gout1 + (size_t)w * 384);
#pragma unroll
    for (int i = 0; i < 3; i++) {
        int c4 = lane + 32 * i;
        float dh = __shfl_sync(0xffffffffu, den, c4 / 12);
        float inv = 1.f / (dh + 1e-16f);
        od[c4] = make_float4(acc[i].x * inv, acc[i].y * inv, acc[i].z * inv, acc[i].w * inv);
    }
}

__global__ void gath2k() {
    int w = (blockIdx.x * blockDim.x + threadIdx.x) >> 5;
    if (w >= NN) return;
    int lane = threadIdx.x & 31;
    int beg = g_off[w], end = g_off[w + 1];
    float ad = g_ad2[w];
    float den = 0.f;
    float4 acc[2];
    acc[0] = make_float4(0.f, 0.f, 0.f, 0.f);
    acc[1] = make_float4(0.f, 0.f, 0.f, 0.f);

    int s = g_srcl[beg];
    for (int j = beg; j < end; j++) {
        int snext = (j + 1 < end) ? g_srcl[j + 1] : 0;
        float ex = __expf(leaky(g_as2[s] + ad));   // identical across lanes
        den += ex;
        const float4* hs = (const float4*)(g_h2 + (size_t)s * 256);
#pragma unroll
        for (int i = 0; i < 2; i++) {
            float4 v = hs[lane + 32 * i];
            acc[i].x += v.x * ex; acc[i].y += v.y * ex;
            acc[i].z += v.z * ex; acc[i].w += v.w * ex;
        }
        s = snext;
    }
    float inv = 1.f / (den + 1e-16f);
    float4* od = (float4*)(g_gout2 + (size_t)w * 256);
#pragma unroll
    for (int i = 0; i < 2; i++)
        od[lane + 32 * i] = make_float4(acc[i].x * inv, acc[i].y * inv,
                                        acc[i].z * inv, acc[i].w * inv);
}

// ---------------- batch norm (partials, no atomics) ----------------
__global__ void bnp(const float* __restrict__ X, int C,
                    float* __restrict__ psum, float* __restrict__ pss) {
    int col = blockIdx.x * 32 + threadIdx.x;
    float s = 0.f, q = 0.f;
    for (int r = threadIdx.y + blockIdx.y * 8; r < NN; r += 8 * gridDim.y) {
        float v = X[(size_t)r * C + col];
        s += v; q += v * v;
    }
    __shared__ float sh[8][32], sh2[8][32];
    sh[threadIdx.y][threadIdx.x] = s;
    sh2[threadIdx.y][threadIdx.x] = q;
    __syncthreads();
    if (threadIdx.y == 0) {
#pragma unroll
        for (int y = 1; y < 8; y++) { s += sh[y][threadIdx.x]; q += sh2[y][threadIdx.x]; }
        psum[blockIdx.y * C + col] = s;
        pss[blockIdx.y * C + col] = q;
    }
}

__global__ void bnf(int C, const float* __restrict__ psum, const float* __restrict__ pss,
                    float* __restrict__ mu, float* __restrict__ rs) {
    int c = blockIdx.x * blockDim.x + threadIdx.x;
    if (c >= C) return;
    float s = 0.f, q = 0.f;
#pragma unroll
    for (int y = 0; y < 16; y++) { s += psum[y * C + c]; q += pss[y * C + c]; }
    float m = s * (1.f / NN);
    float v = q * (1.f / NN) - m * m;
    mu[c] = m;
    rs[c] = rsqrtf(v + 1e-5f);
}

// hr = relu(residual + (gout - mu)*rstd*gamma + beta)
__global__ void fuse1k(const float* __restrict__ x,
                       const float* __restrict__ g, const float* __restrict__ b) {
    int idx = blockIdx.x * blockDim.x + threadIdx.x;
    if (idx >= NN * 384) return;
    int c = idx % 384;
    float val = (g_gout1[idx] - g_mu1[c]) * g_rs1[c] * g[c] + b[c];
    float h = x[idx] + val;
    g_hr1[idx] = h > 0.f ? h : 0.f;
}
__global__ void fuse2k(const float* __restrict__ g, const float* __restrict__ b) {
    int idx = blockIdx.x * blockDim.x + threadIdx.x;
    if (idx >= NN * 256) return;
    int c = idx & 255;
    float val = (g_gout2[idx] - g_mu2[c]) * g_rs2[c] * g[c] + b[c];
    float h = g_h5[idx] + val;
    g_hr2[idx] = h > 0.f ? h : 0.f;
}

// ---------------- pair head ----------------
__global__ void pairk(const int* __restrict__ ei, const int* __restrict__ tid,
                      const float* __restrict__ w4, const float* __restrict__ b4,
                      float* __restrict__ out) {
    int gw = (blockIdx.x * blockDim.x + threadIdx.x) >> 5;
    if (gw >= TEN) return;
    int lane = threadIdx.x & 31;
    int e = tid[gw];
    int s = ei[e], d = ei[EE + e];
    const float* hs = g_hf + (size_t)s * 256;
    const float* hd = g_hf + (size_t)d * 256;
    float acc[7] = {};
#pragma unroll
    for (int k = 0; k < 8; k++) {
        int c = lane + 32 * k;
        float p = hs[c] * hd[c];
        const float* wr = &w4[c * 7];
#pragma unroll
        for (int j = 0; j < 7; j++) acc[j] += p * wr[j];
    }
#pragma unroll
    for (int j = 0; j < 7; j++)
#pragma unroll
        for (int off = 16; off; off >>= 1)
            acc[j] += __shfl_down_sync(0xffffffffu, acc[j], off);
    if (lane == 0) {
#pragma unroll
        for (int j = 0; j < 7; j++) out[(size_t)gw * 7 + j] = acc[j] + b4[j];
    }
}

// ---------------- launch ----------------
extern "C" void kernel_launch(void* const* d_in, const int* in_sizes, int n_in,
                              void* d_out, int out_size) {
    const float* x       = (const float*)d_in[0];
    const int*   ei      = (const int*)d_in[1];
    const int*   teid    = (const int*)d_in[2];
    const float* fc1_w   = (const float*)d_in[3];
    const float* fc1_b   = (const float*)d_in[4];
    const float* fc5_w   = (const float*)d_in[5];
    const float* fc5_b   = (const float*)d_in[6];
    const float* fc2_w   = (const float*)d_in[7];
    const float* fc2_b   = (const float*)d_in[8];
    const float* fc4_w   = (const float*)d_in[9];
    const float* fc4_b   = (const float*)d_in[10];
    const float* gat1_w  = (const float*)d_in[11];
    const float* gat1_as = (const float*)d_in[12];
    const float* gat1_ad = (const float*)d_in[13];
    /* gat1_b unused: BN-invariant */
    const float* gat2_w  = (const float*)d_in[15];
    const float* gat2_as = (const float*)d_in[16];
    const float* gat2_ad = (const float*)d_in[17];
    /* gat2_b unused: BN-invariant */
    const float* bn1_g   = (const float*)d_in[19];
    const float* bn1_b   = (const float*)d_in[20];
    const float* bn2_g   = (const float*)d_in[21];
    const float* bn2_b   = (const float*)d_in[22];
    float* out = (float*)d_out;

    float *p_w1c, *p_b1c, *p_h1, *p_hr1, *p_h5, *p_h2, *p_hr2, *p_hf;
    float *p_gout1, *p_gout2;
    float *p_psum1, *p_pss1, *p_mu1, *p_rs1, *p_psum2, *p_pss2, *p_mu2, *p_rs2;
    cudaGetSymbolAddress((void**)&p_w1c, g_w1c);
    cudaGetSymbolAddress((void**)&p_b1c, g_b1c);
    cudaGetSymbolAddress((void**)&p_h1, g_h1);
    cudaGetSymbolAddress((void**)&p_hr1, g_hr1);
    cudaGetSymbolAddress((void**)&p_h5, g_h5);
    cudaGetSymbolAddress((void**)&p_h2, g_h2);
    cudaGetSymbolAddress((void**)&p_hr2, g_hr2);
    cudaGetSymbolAddress((void**)&p_hf, g_hf);
    cudaGetSymbolAddress((void**)&p_gout1, g_gout1);
    cudaGetSymbolAddress((void**)&p_gout2, g_gout2);
    cudaGetSymbolAddress((void**)&p_psum1, g_psum1);
    cudaGetSymbolAddress((void**)&p_pss1, g_pss1);
    cudaGetSymbolAddress((void**)&p_mu1, g_mu1);
    cudaGetSymbolAddress((void**)&p_rs1, g_rs1);
    cudaGetSymbolAddress((void**)&p_psum2, g_psum2);
    cudaGetSymbolAddress((void**)&p_pss2, g_pss2);
    cudaGetSymbolAddress((void**)&p_mu2, g_mu2);
    cudaGetSymbolAddress((void**)&p_rs2, g_rs2);

    const int MB = (NN + 127) / 128;  // 79

    // weight fusion + CSR build (graph-only work, shared by both layers)
    zerok<<<(384 * 384 + 255) / 256, 256>>>();
    gemm64sk<<<dim3(6, 6, 4), dim3(16, 16)>>>(fc1_w, gat1_w, p_w1c, 384, 384, 384);
    biascomb<<<3, 128>>>(fc1_b, gat1_w);
    degk<<<(EA + 255) / 256, 256>>>(ei);
    scank<<<1, 1024>>>();
    fillk<<<(EA + 255) / 256, 256>>>(ei);

    // h1 = x @ w1c + b1c
    gemm_tf32<<<dim3(3, MB), 256>>>(x, p_w1c, p_b1c, p_h1, NN, 384, 384);

    coef1k<<<(NN + 7) / 8, 256>>>(gat1_as, gat1_ad);
    gath1k<<<(NN * 32 + 255) / 256, 256>>>();

    bnp<<<dim3(12, 16), dim3(32, 8)>>>(p_gout1, 384, p_psum1, p_pss1);
    bnf<<<2, 256>>>(384, p_psum1, p_pss1, p_mu1, p_rs1);
    fuse1k<<<(NN * 384 + 255) / 256, 256>>>(x, bn1_g, bn1_b);

    // h5 = hr1 @ fc5_w + fc5_b ; h2 = h5 @ gat2_w
    gemm_tf32<<<dim3(2, MB), 256>>>(p_hr1, fc5_w, fc5_b, p_h5, NN, 384, 256);
    gemm_tf32<<<dim3(2, MB), 256>>>(p_h5, gat2_w, nullptr, p_h2, NN, 256, 256);

    coef2k<<<(NN * 32 + 255) / 256, 256>>>(gat2_as, gat2_ad);
    gath2k<<<(NN * 32 + 255) / 256, 256>>>();

    bnp<<<dim3(8, 16), dim3(32, 8)>>>(p_gout2, 256, p_psum2, p_pss2);
    bnf<<<1, 256>>>(256, p_psum2, p_pss2, p_mu2, p_rs2);
    fuse2k<<<(NN * 256 + 255) / 256, 256>>>(bn2_g, bn2_b);

    // hf = hr2 @ fc2_w + fc2_b
    gemm_tf32<<<dim3(2, MB), 256>>>(p_hr2, fc2_w, fc2_b, p_hf, NN, 256, 256);

    // pair head
    pairk<<<(TEN * 32 + 255) / 256, 256>>>(ei, teid, fc4_w, fc4_b, out);
}

// round 6
// speedup vs baseline: 1.8338x; 1.0138x over previous
#include <cuda_runtime.h>
#include <cuda_bf16.h>
#include <cstdint>

#define NN 10000
#define EE 160000
#define TEN 65536
#define EA (EE + NN)   // edges + self loops = 170000

// ---------------- scratch (static device globals; no allocation) ----------------
__device__ float g_w1c[384 * 384];    // fc1_w @ gat1_w (tf32-rounded after fuse)
__device__ float g_b1c[384];          // fc1_b @ gat1_w
__device__ float g_w5r[384 * 256];    // tf32-rounded fc5_w
__device__ float g_wg2r[256 * 256];   // tf32-rounded gat2_w
__device__ float g_w2r[256 * 256];    // tf32-rounded fc2_w
__device__ float g_h1[NN * 384];      // gat1 h = x @ w1c + b1c
__device__ float g_gout1[NN * 384];   // gat1 normalized aggregate
__device__ float g_hr1[NN * 384];     // relu(x + bn1)
__device__ float g_h5[NN * 256];      // fc5 out
__device__ float g_h2[NN * 256];      // gat2 h
__device__ float g_gout2[NN * 256];
__device__ float g_hr2[NN * 256];     // relu(h5 + bn2)
__device__ float g_hf[NN * 256];      // fc2 out

__device__ float g_as1[NN * 8], g_ad1[NN * 8];
__device__ float g_as2[NN], g_ad2[NN];
__device__ float g_psum1[16 * 384], g_pss1[16 * 384], g_mu1[384], g_rs1[384];
__device__ float g_psum2[16 * 256], g_pss2[16 * 256], g_mu2[256], g_rs2[256];

// CSR by destination (shared by both GAT layers)
__device__ int g_deg[NN];
__device__ int g_off[NN + 1];
__device__ int g_pos[NN];
__device__ int g_srcl[EA];

// ---------------- helpers ----------------
__device__ __forceinline__ void edge_sd(const int* __restrict__ ei, int e, int& s, int& d) {
    if (e < EE) { s = ei[e]; d = ei[EE + e]; }
    else        { s = e - EE; d = e - EE; }
}

__device__ __forceinline__ float leaky(float v) { return v > 0.f ? v : 0.2f * v; }

__device__ __forceinline__ uint32_t f2tf32(float v) {
    uint32_t u;
    asm("cvt.rna.tf32.f32 %0, %1;" : "=r"(u) : "f"(v));
    return u;
}

// elementwise tf32 rounding (weights pre-rounded once; bit-identical to in-GEMM cvt)
__global__ void roundw(const float* __restrict__ W, float* __restrict__ R, int n) {
    int i = blockIdx.x * blockDim.x + threadIdx.x;
    if (i < n) R[i] = __uint_as_float(f2tf32(W[i]));
}

// ---------------- TF32 tensor-core GEMM; B must be pre-rounded to tf32 --------
__global__ void __launch_bounds__(256) gemm_tf32(
    const float* __restrict__ A, const float* __restrict__ B,
    const float* __restrict__ bias, float* __restrict__ C,
    int M, int K, int Nc)
{
    __shared__ uint32_t As[128 * 36];
    __shared__ uint32_t Bs[32 * 136];
    const int t = threadIdx.x, lane = t & 31, wid = t >> 5;
    const int wm = (wid & 1) * 64, wn = (wid >> 1) * 32;
    const int m0 = blockIdx.y * 128, n0 = blockIdx.x * 128;
    const uint32_t* Bu = (const uint32_t*)B;
    float acc[4][4][4];
#pragma unroll
    for (int i = 0; i < 4; i++)
#pragma unroll
        for (int j = 0; j < 4; j++)
#pragma unroll
            for (int q = 0; q < 4; q++) acc[i][j][q] = 0.f;

    for (int k0 = 0; k0 < K; k0 += 32) {
#pragma unroll
        for (int j = 0; j < 4; j++) {
            int idx = t + 256 * j;
            int row = idx >> 3, kc = (idx & 7) * 4;
            float4 v = make_float4(0.f, 0.f, 0.f, 0.f);
            if (m0 + row < M)
                v = *(const float4*)&A[(size_t)(m0 + row) * K + k0 + kc];
            uint4 u = make_uint4(f2tf32(v.x), f2tf32(v.y), f2tf32(v.z), f2tf32(v.w));
            *(uint4*)&As[row * 36 + kc] = u;
        }
#pragma unroll
        for (int j = 0; j < 4; j++) {
            int idx = t + 256 * j;
            int kr = idx >> 5, nc = (idx & 31) * 4;
            uint4 u = *(const uint4*)&Bu[(size_t)(k0 + kr) * Nc + n0 + nc];
            *(uint4*)&Bs[kr * 136 + nc] = u;
        }
        __syncthreads();
#pragma unroll
        for (int ks = 0; ks < 4; ks++) {
            uint32_t af[4][4], bf[4][2];
            const int kk = ks * 8 + (lane & 3);
#pragma unroll
            for (int mt = 0; mt < 4; mt++) {
                int m = wm + mt * 16 + (lane >> 2);
                af[mt][0] = As[m * 36 + kk];
                af[mt][1] = As[(m + 8) * 36 + kk];
                af[mt][2] = As[m * 36 + kk + 4];
                af[mt][3] = As[(m + 8) * 36 + kk + 4];
            }
#pragma unroll
            for (int nt = 0; nt < 4; nt++) {
                int n = wn + nt * 8 + (lane >> 2);
                bf[nt][0] = Bs[kk * 136 + n];
                bf[nt][1] = Bs[(kk + 4) * 136 + n];
            }
#pragma unroll
            for (int mt = 0; mt < 4; mt++)
#pragma unroll
                for (int nt = 0; nt < 4; nt++) {
                    asm volatile(
                        "mma.sync.aligned.m16n8k8.row.col.f32.tf32.tf32.f32 "
                        "{%0,%1,%2,%3}, {%4,%5,%6,%7}, {%8,%9}, {%0,%1,%2,%3};\n"
                        : "+f"(acc[mt][nt][0]), "+f"(acc[mt][nt][1]),
                          "+f"(acc[mt][nt][2]), "+f"(acc[mt][nt][3])
                        : "r"(af[mt][0]), "r"(af[mt][1]), "r"(af[mt][2]), "r"(af[mt][3]),
                          "r"(bf[nt][0]), "r"(bf[nt][1]));
                }
        }
        __syncthreads();
    }
#pragma unroll
    for (int mt = 0; mt < 4; mt++) {
#pragma unroll
        for (int nt = 0; nt < 4; nt++) {
            int r = m0 + wm + mt * 16 + (lane >> 2);
            int c = n0 + wn + nt * 8 + 2 * (lane & 3);
            float b0 = bias ? bias[c] : 0.f;
            float b1 = bias ? bias[c + 1] : 0.f;
            if (r < M) {
                float2 v = make_float2(acc[mt][nt][0] + b0, acc[mt][nt][1] + b1);
                *(float2*)&C[(size_t)r * Nc + c] = v;
            }
            if (r + 8 < M) {
                float2 v = make_float2(acc[mt][nt][2] + b0, acc[mt][nt][3] + b1);
                *(float2*)&C[(size_t)(r + 8) * Nc + c] = v;
            }
        }
    }
}

// ---------------- fp32 split-K GEMM for the 384^3 weight fuse ------------------
__global__ void gemm64sk(const float* __restrict__ A, const float* __restrict__ B,
                         float* __restrict__ C, int M, int K, int Nc) {
    __shared__ float As[16][64];
    __shared__ float Bs[16][64];
    const int tx = threadIdx.x, ty = threadIdx.y;
    const int t = ty * 16 + tx;
    const int m0 = blockIdx.y * 64, n0 = blockIdx.x * 64;
    const int Kc = K / gridDim.z;
    const int kbeg = blockIdx.z * Kc, kend = kbeg + Kc;
    const int la_m = t >> 2, la_k = (t & 3) * 4;
    const int lb_k = t >> 4, lb_n = (t & 15) * 4;
    float acc[4][4] = {};
    for (int k0 = kbeg; k0 < kend; k0 += 16) {
        float4 av = *(const float4*)&A[(size_t)(m0 + la_m) * K + k0 + la_k];
        As[la_k + 0][la_m] = av.x; As[la_k + 1][la_m] = av.y;
        As[la_k + 2][la_m] = av.z; As[la_k + 3][la_m] = av.w;
        *(float4*)&Bs[lb_k][lb_n] =
            *(const float4*)&B[(size_t)(k0 + lb_k) * Nc + n0 + lb_n];
        __syncthreads();
#pragma unroll
        for (int kk = 0; kk < 16; kk++) {
            float4 a = *(const float4*)&As[kk][ty * 4];
            float4 b = *(const float4*)&Bs[kk][tx * 4];
            float ar[4] = {a.x, a.y, a.z, a.w};
            float br[4] = {b.x, b.y, b.z, b.w};
#pragma unroll
            for (int i = 0; i < 4; i++)
#pragma unroll
                for (int j = 0; j < 4; j++) acc[i][j] += ar[i] * br[j];
        }
        __syncthreads();
    }
#pragma unroll
    for (int i = 0; i < 4; i++)
#pragma unroll
        for (int j = 0; j < 4; j++)
            atomicAdd(&C[(size_t)(m0 + ty * 4 + i) * Nc + n0 + tx * 4 + j], acc[i][j]);
}

// zero w1c + degree counters
__global__ void zerok() {
    int i = blockIdx.x * blockDim.x + threadIdx.x;
    if (i < 384 * 384) g_w1c[i] = 0.f;
    if (i < NN) g_deg[i] = 0;
}

// b1c[j] = sum_k fc1_b[k] * gat1_w[k][j]
__global__ void biascomb(const float* __restrict__ fb, const float* __restrict__ W) {
    int j = blockIdx.x * blockDim.x + threadIdx.x;
    if (j >= 384) return;
    float s = 0.f;
    for (int k = 0; k < 384; k++) s += fb[k] * W[k * 384 + j];
    g_b1c[j] = s;
}

// ---------------- CSR build ----------------
__global__ void degk(const int* __restrict__ ei) {
    int e = blockIdx.x * blockDim.x + threadIdx.x;
    if (e >= EA) return;
    int s, d;
    edge_sd(ei, e, s, d);
    atomicAdd(&g_deg[d], 1);
}

// single-block exclusive scan of g_deg -> g_off; zeros g_pos
__global__ void __launch_bounds__(1024) scank() {
    __shared__ int sums[1024];
    const int t = threadIdx.x;
    const int CH = (NN + 1023) / 1024;   // 10
    int vals[(NN + 1023) / 1024];
    int base = t * CH;
    int local = 0;
#pragma unroll
    for (int i = 0; i < CH; i++) {
        int idx = base + i;
        int v = (idx < NN) ? g_deg[idx] : 0;
        vals[i] = v;
        local += v;
    }
    sums[t] = local;
    __syncthreads();
    for (int off = 1; off < 1024; off <<= 1) {
        int v = (t >= off) ? sums[t - off] : 0;
        __syncthreads();
        sums[t] += v;
        __syncthreads();
    }
    int prefix = (t == 0) ? 0 : sums[t - 1];
#pragma unroll
    for (int i = 0; i < CH; i++) {
        int idx = base + i;
        if (idx < NN) { g_off[idx] = prefix; prefix += vals[i]; }
    }
    if (t == 1023) g_off[NN] = prefix;
    for (int i = t; i < NN; i += 1024) g_pos[i] = 0;
}

__global__ void fillk(const int* __restrict__ ei) {
    int e = blockIdx.x * blockDim.x + threadIdx.x;
    if (e >= EA) return;
    int s, d;
    edge_sd(ei, e, s, d);
    int slot = atomicAdd(&g_pos[d], 1);
    g_srcl[g_off[d] + slot] = s;
}

// ---------------- GAT coefficients ----------------
// warp per node; 4 lanes per head; shfl reduction (no smem, no atomics)
__global__ void coef1k(const float* __restrict__ asw, const float* __restrict__ adw) {
    int w = (blockIdx.x * blockDim.x + threadIdx.x) >> 5;
    if (w >= NN) return;
    int lane = threadIdx.x & 31;
    int hd = lane >> 2;       // 0..7 (head)
    int l2 = lane & 3;        // 0..3 (lane within head group)
    const float4* hp = (const float4*)(g_h1 + (size_t)w * 384);
    const float4* ap = (const float4*)asw;   // (8,48) flat == h chunk layout
    const float4* dp = (const float4*)adw;
    float s = 0.f, d = 0.f;
#pragma unroll
    for (int i = 0; i < 3; i++) {
        int c4 = hd * 12 + l2 + 4 * i;   // 12 float4s per head, 3 per lane
        float4 v = hp[c4], a = ap[c4], dd = dp[c4];
        s += v.x * a.x + v.y * a.y + v.z * a.z + v.w * a.w;
        d += v.x * dd.x + v.y * dd.y + v.z * dd.z + v.w * dd.w;
    }
    s += __shfl_xor_sync(0xffffffffu, s, 1);
    s += __shfl_xor_sync(0xffffffffu, s, 2);
    d += __shfl_xor_sync(0xffffffffu, d, 1);
    d += __shfl_xor_sync(0xffffffffu, d, 2);
    if (l2 == 0) {
        g_as1[w * 8 + hd] = s;
        g_ad1[w * 8 + hd] = d;
    }
}

__global__ void coef2k(const float* __restrict__ asw, const float* __restrict__ adw) {
    int gw = (blockIdx.x * blockDim.x + threadIdx.x) >> 5;
    if (gw >= NN) return;
    int lane = threadIdx.x & 31;
    const float* hp = g_h2 + (size_t)gw * 256;
    float s = 0.f, d = 0.f;
#pragma unroll
    for (int k = 0; k < 8; k++) {
        int c = lane + 32 * k;
        float v = hp[c];
        s += v * asw[c]; d += v * adw[c];
    }
#pragma unroll
    for (int off = 16; off; off >>= 1) {
        s += __shfl_down_sync(0xffffffffu, s, off);
        d += __shfl_down_sync(0xffffffffu, d, off);
    }
    if (lane == 0) { g_as2[gw] = s; g_ad2[gw] = d; }
}

// ---------------- CSR gather aggregation (no atomics, normalized output) ------
__global__ void gath1k() {
    int w = (blockIdx.x * blockDim.x + threadIdx.x) >> 5;
    if (w >= NN) return;
    int lane = threadIdx.x & 31;
    int beg = g_off[w], end = g_off[w + 1];   // end > beg (self-loop guarantees)
    float ad = (lane < 8) ? g_ad1[w * 8 + lane] : 0.f;
    float den = 0.f;
    float4 acc[3];
#pragma unroll
    for (int i = 0; i < 3; i++) acc[i] = make_float4(0.f, 0.f, 0.f, 0.f);

    int s = g_srcl[beg];
    for (int j = beg; j < end; j++) {
        int snext = (j + 1 < end) ? g_srcl[j + 1] : 0;
        float ex = 0.f;
        if (lane < 8) {
            ex = __expf(leaky(g_as1[s * 8 + lane] + ad));
            den += ex;
        }
        const float4* hs = (const float4*)(g_h1 + (size_t)s * 384);
#pragma unroll
        for (int i = 0; i < 3; i++) {
            int c4 = lane + 32 * i;
            float a = __shfl_sync(0xffffffffu, ex, c4 / 12);
            float4 v = hs[c4];
            acc[i].x += v.x * a; acc[i].y += v.y * a;
            acc[i].z += v.z * a; acc[i].w += v.w * a;
        }
        s = snext;
    }
    float4* od = (float4*)(g_gout1 + (size_t)w * 384);
#pragma unroll
    for (int i = 0; i < 3; i++) {
        int c4 = lane + 32 * i;
        float dh = __shfl_sync(0xffffffffu, den, c4 / 12);
        float inv = 1.f / (dh + 1e-16f);
        od[c4] = make_float4(acc[i].x * inv, acc[i].y * inv, acc[i].z * inv, acc[i].w * inv);
    }
}

__global__ void gath2k() {
    int w = (blockIdx.x * blockDim.x + threadIdx.x) >> 5;
    if (w >= NN) return;
    int lane = threadIdx.x & 31;
    int beg = g_off[w], end = g_off[w + 1];
    float ad = g_ad2[w];
    float den = 0.f;
    float4 acc[2];
    acc[0] = make_float4(0.f, 0.f, 0.f, 0.f);
    acc[1] = make_float4(0.f, 0.f, 0.f, 0.f);

    int s = g_srcl[beg];
    for (int j = beg; j < end; j++) {
        int snext = (j + 1 < end) ? g_srcl[j + 1] : 0;
        float ex = __expf(leaky(g_as2[s] + ad));   // identical across lanes
        den += ex;
        const float4* hs = (const float4*)(g_h2 + (size_t)s * 256);
#pragma unroll
        for (int i = 0; i < 2; i++) {
            float4 v = hs[lane + 32 * i];
            acc[i].x += v.x * ex; acc[i].y += v.y * ex;
            acc[i].z += v.z * ex; acc[i].w += v.w * ex;
        }
        s = snext;
    }
    float inv = 1.f / (den + 1e-16f);
    float4* od = (float4*)(g_gout2 + (size_t)w * 256);
#pragma unroll
    for (int i = 0; i < 2; i++)
        od[lane + 32 * i] = make_float4(acc[i].x * inv, acc[i].y * inv,
                                        acc[i].z * inv, acc[i].w * inv);
}

// ---------------- batch norm (partials, no atomics) ----------------
__global__ void bnp(const float* __restrict__ X, int C,
                    float* __restrict__ psum, float* __restrict__ pss) {
    int col = blockIdx.x * 32 + threadIdx.x;
    float s = 0.f, q = 0.f;
    for (int r = threadIdx.y + blockIdx.y * 8; r < NN; r += 8 * gridDim.y) {
        float v = X[(size_t)r * C + col];
        s += v; q += v * v;
    }
    __shared__ float sh[8][32], sh2[8][32];
    sh[threadIdx.y][threadIdx.x] = s;
    sh2[threadIdx.y][threadIdx.x] = q;
    __syncthreads();
    if (threadIdx.y == 0) {
#pragma unroll
        for (int y = 1; y < 8; y++) { s += sh[y][threadIdx.x]; q += sh2[y][threadIdx.x]; }
        psum[blockIdx.y * C + col] = s;
        pss[blockIdx.y * C + col] = q;
    }
}

__global__ void bnf(int C, const float* __restrict__ psum, const float* __restrict__ pss,
                    float* __restrict__ mu, float* __restrict__ rs) {
    int c = blockIdx.x * blockDim.x + threadIdx.x;
    if (c >= C) return;
    float s = 0.f, q = 0.f;
#pragma unroll
    for (int y = 0; y < 16; y++) { s += psum[y * C + c]; q += pss[y * C + c]; }
    float m = s * (1.f / NN);
    float v = q * (1.f / NN) - m * m;
    mu[c] = m;
    rs[c] = rsqrtf(v + 1e-5f);
}

// hr = relu(residual + (gout - mu)*rstd*gamma + beta)
__global__ void fuse1k(const float* __restrict__ x,
                       const float* __restrict__ g, const float* __restrict__ b) {
    int idx = blockIdx.x * blockDim.x + threadIdx.x;
    if (idx >= NN * 384) return;
    int c = idx % 384;
    float val = (g_gout1[idx] - g_mu1[c]) * g_rs1[c] * g[c] + b[c];
    float h = x[idx] + val;
    g_hr1[idx] = h > 0.f ? h : 0.f;
}
__global__ void fuse2k(const float* __restrict__ g, const float* __restrict__ b) {
    int idx = blockIdx.x * blockDim.x + threadIdx.x;
    if (idx >= NN * 256) return;
    int c = idx & 255;
    float val = (g_gout2[idx] - g_mu2[c]) * g_rs2[c] * g[c] + b[c];
    float h = g_h5[idx] + val;
    g_hr2[idx] = h > 0.f ? h : 0.f;
}

// ---------------- pair head ----------------
__global__ void pairk(const int* __restrict__ ei, const int* __restrict__ tid,
                      const float* __restrict__ w4, const float* __restrict__ b4,
                      float* __restrict__ out) {
    int gw = (blockIdx.x * blockDim.x + threadIdx.x) >> 5;
    if (gw >= TEN) return;
    int lane = threadIdx.x & 31;
    int e = tid[gw];
    int s = ei[e], d = ei[EE + e];
    const float* hs = g_hf + (size_t)s * 256;
    const float* hd = g_hf + (size_t)d * 256;
    float acc[7] = {};
#pragma unroll
    for (int k = 0; k < 8; k++) {
        int c = lane + 32 * k;
        float p = hs[c] * hd[c];
        const float* wr = &w4[c * 7];
#pragma unroll
        for (int j = 0; j < 7; j++) acc[j] += p * wr[j];
    }
#pragma unroll
    for (int j = 0; j < 7; j++)
#pragma unroll
        for (int off = 16; off; off >>= 1)
            acc[j] += __shfl_down_sync(0xffffffffu, acc[j], off);
    if (lane == 0) {
#pragma unroll
        for (int j = 0; j < 7; j++) out[(size_t)gw * 7 + j] = acc[j] + b4[j];
    }
}

// ---------------- launch ----------------
extern "C" void kernel_launch(void* const* d_in, const int* in_sizes, int n_in,
                              void* d_out, int out_size) {
    const float* x       = (const float*)d_in[0];
    const int*   ei      = (const int*)d_in[1];
    const int*   teid    = (const int*)d_in[2];
    const float* fc1_w   = (const float*)d_in[3];
    const float* fc1_b   = (const float*)d_in[4];
    const float* fc5_w   = (const float*)d_in[5];
    const float* fc5_b   = (const float*)d_in[6];
    const float* fc2_w   = (const float*)d_in[7];
    const float* fc2_b   = (const float*)d_in[8];
    const float* fc4_w   = (const float*)d_in[9];
    const float* fc4_b   = (const float*)d_in[10];
    const float* gat1_w  = (const float*)d_in[11];
    const float* gat1_as = (const float*)d_in[12];
    const float* gat1_ad = (const float*)d_in[13];
    /* gat1_b unused: BN-invariant */
    const float* gat2_w  = (const float*)d_in[15];
    const float* gat2_as = (const float*)d_in[16];
    const float* gat2_ad = (const float*)d_in[17];
    /* gat2_b unused: BN-invariant */
    const float* bn1_g   = (const float*)d_in[19];
    const float* bn1_b   = (const float*)d_in[20];
    const float* bn2_g   = (const float*)d_in[21];
    const float* bn2_b   = (const float*)d_in[22];
    float* out = (float*)d_out;

    float *p_w1c, *p_b1c, *p_w5r, *p_wg2r, *p_w2r;
    float *p_h1, *p_hr1, *p_h5, *p_h2, *p_hr2, *p_hf, *p_gout1, *p_gout2;
    float *p_psum1, *p_pss1, *p_mu1, *p_rs1, *p_psum2, *p_pss2, *p_mu2, *p_rs2;
    cudaGetSymbolAddress((void**)&p_w1c, g_w1c);
    cudaGetSymbolAddress((void**)&p_b1c, g_b1c);
    cudaGetSymbolAddress((void**)&p_w5r, g_w5r);
    cudaGetSymbolAddress((void**)&p_wg2r, g_wg2r);
    cudaGetSymbolAddress((void**)&p_w2r, g_w2r);
    cudaGetSymbolAddress((void**)&p_h1, g_h1);
    cudaGetSymbolAddress((void**)&p_hr1, g_hr1);
    cudaGetSymbolAddress((void**)&p_h5, g_h5);
    cudaGetSymbolAddress((void**)&p_h2, g_h2);
    cudaGetSymbolAddress((void**)&p_hr2, g_hr2);
    cudaGetSymbolAddress((void**)&p_hf, g_hf);
    cudaGetSymbolAddress((void**)&p_gout1, g_gout1);
    cudaGetSymbolAddress((void**)&p_gout2, g_gout2);
    cudaGetSymbolAddress((void**)&p_psum1, g_psum1);
    cudaGetSymbolAddress((void**)&p_pss1, g_pss1);
    cudaGetSymbolAddress((void**)&p_mu1, g_mu1);
    cudaGetSymbolAddress((void**)&p_rs1, g_rs1);
    cudaGetSymbolAddress((void**)&p_psum2, g_psum2);
    cudaGetSymbolAddress((void**)&p_pss2, g_pss2);
    cudaGetSymbolAddress((void**)&p_mu2, g_mu2);
    cudaGetSymbolAddress((void**)&p_rs2, g_rs2);

    const int MB = (NN + 127) / 128;  // 79

    // weight fusion + weight rounding + CSR build
    zerok<<<(384 * 384 + 255) / 256, 256>>>();
    gemm64sk<<<dim3(6, 6, 4), dim3(16, 16)>>>(fc1_w, gat1_w, p_w1c, 384, 384, 384);
    biascomb<<<3, 128>>>(fc1_b, gat1_w);
    roundw<<<(384 * 384 + 255) / 256, 256>>>(p_w1c, p_w1c, 384 * 384);
    roundw<<<(384 * 256 + 255) / 256, 256>>>(fc5_w, p_w5r, 384 * 256);
    roundw<<<(256 * 256 + 255) / 256, 256>>>(gat2_w, p_wg2r, 256 * 256);
    roundw<<<(256 * 256 + 255) / 256, 256>>>(fc2_w, p_w2r, 256 * 256);
    degk<<<(EA + 255) / 256, 256>>>(ei);
    scank<<<1, 1024>>>();
    fillk<<<(EA + 255) / 256, 256>>>(ei);

    // h1 = x @ w1c + b1c
    gemm_tf32<<<dim3(3, MB), 256>>>(x, p_w1c, p_b1c, p_h1, NN, 384, 384);

    coef1k<<<(NN * 32 + 255) / 256, 256>>>(gat1_as, gat1_ad);
    gath1k<<<(NN * 32 + 255) / 256, 256>>>();

    bnp<<<dim3(12, 16), dim3(32, 8)>>>(p_gout1, 384, p_psum1, p_pss1);
    bnf<<<2, 256>>>(384, p_psum1, p_pss1, p_mu1, p_rs1);
    fuse1k<<<(NN * 384 + 255) / 256, 256>>>(x, bn1_g, bn1_b);

    // h5 = hr1 @ fc5_w + fc5_b ; h2 = h5 @ gat2_w
    gemm_tf32<<<dim3(2, MB), 256>>>(p_hr1, p_w5r, fc5_b, p_h5, NN, 384, 256);
    gemm_tf32<<<dim3(2, MB), 256>>>(p_h5, p_wg2r, nullptr, p_h2, NN, 256, 256);

    coef2k<<<(NN * 32 + 255) / 256, 256>>>(gat2_as, gat2_ad);
    gath2k<<<(NN * 32 + 255) / 256, 256>>>();

    bnp<<<dim3(8, 16), dim3(32, 8)>>>(p_gout2, 256, p_psum2, p_pss2);
    bnf<<<1, 256>>>(256, p_psum2, p_pss2, p_mu2, p_rs2);
    fuse2k<<<(NN * 256 + 255) / 256, 256>>>(bn2_g, bn2_b);

    // hf = hr2 @ fc2_w + fc2_b
    gemm_tf32<<<dim3(2, MB), 256>>>(p_hr2, p_w2r, fc2_b, p_hf, NN, 256, 256);

    // pair head
    pairk<<<(TEN * 32 + 255) / 256, 256>>>(ei, teid, fc4_w, fc4_b, out);
}

// round 7
// speedup vs baseline: 2.0144x; 1.0985x over previous
#include <cuda_runtime.h>
#include <cuda_bf16.h>
#include <cstdint>

#define NN 10000
#define EE 160000
#define TEN 65536
#define EA (EE + NN)   // edges + self loops = 170000

// ---------------- scratch (static device globals; no allocation) ----------------
__device__ float g_w1c[384 * 384];    // fc1_w @ gat1_w
__device__ float g_b1c[384];          // fc1_b @ gat1_w
__device__ float g_w5r[384 * 256];    // tf32-rounded fc5_w
__device__ float g_wg2r[256 * 256];   // tf32-rounded gat2_w
__device__ float g_w2r[256 * 256];    // tf32-rounded fc2_w
__device__ float g_h1[NN * 384];
__device__ float g_gout1[NN * 384];
__device__ float g_hr1[NN * 384];
__device__ float g_h5[NN * 256];
__device__ float g_h2[NN * 256];
__device__ float g_gout2[NN * 256];
__device__ float g_hr2[NN * 256];
__device__ float g_hf[NN * 256];

__device__ float g_as1[NN * 8], g_ad1[NN * 8];
__device__ float g_as2[NN], g_ad2[NN];
__device__ float g_psum1[16 * 384], g_pss1[16 * 384], g_mu1[384], g_rs1[384];
__device__ float g_psum2[16 * 256], g_pss2[16 * 256], g_mu2[256], g_rs2[256];

// CSR by destination (shared by both GAT layers)
__device__ int g_deg[NN];
__device__ int g_off[NN + 1];
__device__ int g_pos[NN];
__device__ int g_srcl[EA];
__device__ int g_ctr[3];   // [0]=degk blocks, [1]=bnp1 blocks, [2]=bnp2 blocks

// ---------------- helpers ----------------
__device__ __forceinline__ void edge_sd(const int* __restrict__ ei, int e, int& s, int& d) {
    if (e < EE) { s = ei[e]; d = ei[EE + e]; }
    else        { s = e - EE; d = e - EE; }
}

__device__ __forceinline__ float leaky(float v) { return v > 0.f ? v : 0.2f * v; }

__device__ __forceinline__ uint32_t f2tf32(float v) {
    uint32_t u;
    asm("cvt.rna.tf32.f32 %0, %1;" : "=r"(u) : "f"(v));
    return u;
}

// ---------------- setupA: zero accumulators + counters ----------------
__global__ void setupA() {
    int i = blockIdx.x * blockDim.x + threadIdx.x;
    if (i < 384 * 384) g_w1c[i] = 0.f;
    if (i < NN) g_deg[i] = 0;
    if (i < 3) g_ctr[i] = 0;
}

// ---------------- setupB: merged independent prep jobs ----------------
// jobs by block range:
//   [0,144)            gemm64sk: w1c += fc1_w @ gat1_w  (6x6 tiles x 4 K-chunks)
//   [144,146)          biascomb: b1c = fc1_b @ gat1_w
//   [146,530)          round fc5_w   -> w5r   (384 blocks)
//   [530,786)          round gat2_w  -> wg2r  (256)
//   [786,1042)         round fc2_w   -> w2r   (256)
//   [1042,1707)        degk (+ last-block CSR scan)      (665)
#define NB_G 144
#define NB_BC 2
#define NB_R5 384
#define NB_RG 256
#define NB_R2 256
#define NB_DEG 665
#define B_BC   (NB_G)
#define B_R5   (B_BC + NB_BC)
#define B_RG   (B_R5 + NB_R5)
#define B_R2   (B_RG + NB_RG)
#define B_DEG  (B_R2 + NB_R2)
#define NB_ALL (B_DEG + NB_DEG)

__global__ void __launch_bounds__(256) setupB(
    const float* __restrict__ fc1_w, const float* __restrict__ gat1_w,
    const float* __restrict__ fc1_b,
    const float* __restrict__ fc5_w, const float* __restrict__ gat2_w,
    const float* __restrict__ fc2_w, const int* __restrict__ ei)
{
    const int b = blockIdx.x;
    const int t = threadIdx.x;

    if (b < NB_G) {
        // ---- fp32 split-K 384^3 GEMM tile ----
        __shared__ float As[16][64];
        __shared__ float Bs[16][64];
        int q = b;
        int z = q & 3; q >>= 2;
        int bx = q % 6, by = q / 6;
        const int m0 = by * 64, n0 = bx * 64;
        const int kbeg = z * 96, kend = kbeg + 96;
        const int tx = t & 15, ty = t >> 4;
        const int la_m = t >> 2, la_k = (t & 3) * 4;
        const int lb_k = t >> 4, lb_n = (t & 15) * 4;
        float acc[4][4] = {};
        for (int k0 = kbeg; k0 < kend; k0 += 16) {
            float4 av = *(const float4*)&fc1_w[(size_t)(m0 + la_m) * 384 + k0 + la_k];
            As[la_k + 0][la_m] = av.x; As[la_k + 1][la_m] = av.y;
            As[la_k + 2][la_m] = av.z; As[la_k + 3][la_m] = av.w;
            *(float4*)&Bs[lb_k][lb_n] =
                *(const float4*)&gat1_w[(size_t)(k0 + lb_k) * 384 + n0 + lb_n];
            __syncthreads();
#pragma unroll
            for (int kk = 0; kk < 16; kk++) {
                float4 a = *(const float4*)&As[kk][ty * 4];
                float4 bb = *(const float4*)&Bs[kk][tx * 4];
                float ar[4] = {a.x, a.y, a.z, a.w};
                float br[4] = {bb.x, bb.y, bb.z, bb.w};
#pragma unroll
                for (int i = 0; i < 4; i++)
#pragma unroll
                    for (int j = 0; j < 4; j++) acc[i][j] += ar[i] * br[j];
            }
            __syncthreads();
        }
#pragma unroll
        for (int i = 0; i < 4; i++)
#pragma unroll
            for (int j = 0; j < 4; j++)
                atomicAdd(&g_w1c[(size_t)(m0 + ty * 4 + i) * 384 + n0 + tx * 4 + j],
                          acc[i][j]);
    } else if (b < B_R5) {
        int j = (b - B_BC) * 256 + t;
        if (j < 384) {
            float s = 0.f;
            for (int k = 0; k < 384; k++) s += fc1_b[k] * gat1_w[k * 384 + j];
            g_b1c[j] = s;
        }
    } else if (b < B_RG) {
        int i = (b - B_R5) * 256 + t;
        g_w5r[i] = __uint_as_float(f2tf32(fc5_w[i]));
    } else if (b < B_R2) {
        int i = (b - B_RG) * 256 + t;
        g_wg2r[i] = __uint_as_float(f2tf32(gat2_w[i]));
    } else if (b < B_DEG) {
        int i = (b - B_R2) * 256 + t;
        g_w2r[i] = __uint_as_float(f2tf32(fc2_w[i]));
    } else {
        // ---- degree count + last-block exclusive scan ----
        int e = (b - B_DEG) * 256 + t;
        if (e < EA) {
            int s, d;
            edge_sd(ei, e, s, d);
            atomicAdd(&g_deg[d], 1);
        }
        __threadfence();
        __syncthreads();
        __shared__ bool isLast;
        if (t == 0) isLast = (atomicAdd(&g_ctr[0], 1) == NB_DEG - 1);
        __syncthreads();
        if (isLast) {
            __threadfence();
            __shared__ int sums[256];
            const int CH = 40;                 // 256*40 >= NN
            int vals[CH];
            int base = t * CH;
            int local = 0;
#pragma unroll
            for (int i = 0; i < CH; i++) {
                int idx = base + i;
                int v = (idx < NN) ? g_deg[idx] : 0;
                vals[i] = v;
                local += v;
            }
            sums[t] = local;
            __syncthreads();
            for (int off = 1; off < 256; off <<= 1) {
                int v = (t >= off) ? sums[t - off] : 0;
                __syncthreads();
                sums[t] += v;
                __syncthreads();
            }
            int prefix = (t == 0) ? 0 : sums[t - 1];
#pragma unroll
            for (int i = 0; i < CH; i++) {
                int idx = base + i;
                if (idx < NN) { g_off[idx] = prefix; prefix += vals[i]; }
            }
            if (t == 255) g_off[NN] = sums[255];
            for (int i = t; i < NN; i += 256) g_pos[i] = 0;
        }
    }
}

__global__ void fillk(const int* __restrict__ ei) {
    int e = blockIdx.x * blockDim.x + threadIdx.x;
    if (e >= EA) return;
    int s, d;
    edge_sd(ei, e, s, d);
    int slot = atomicAdd(&g_pos[d], 1);
    g_srcl[g_off[d] + slot] = s;
}

// ---------------- TF32 tensor-core GEMM; cvtB picks in-kernel B convert -------
__global__ void __launch_bounds__(256) gemm_tf32(
    const float* __restrict__ A, const float* __restrict__ B,
    const float* __restrict__ bias, float* __restrict__ C,
    int M, int K, int Nc, int cvtB)
{
    __shared__ uint32_t As[128 * 36];
    __shared__ uint32_t Bs[32 * 136];
    const int t = threadIdx.x, lane = t & 31, wid = t >> 5;
    const int wm = (wid & 1) * 64, wn = (wid >> 1) * 32;
    const int m0 = blockIdx.y * 128, n0 = blockIdx.x * 128;
    const uint32_t* Bu = (const uint32_t*)B;
    float acc[4][4][4];
#pragma unroll
    for (int i = 0; i < 4; i++)
#pragma unroll
        for (int j = 0; j < 4; j++)
#pragma unroll
            for (int q = 0; q < 4; q++) acc[i][j][q] = 0.f;

    for (int k0 = 0; k0 < K; k0 += 32) {
#pragma unroll
        for (int j = 0; j < 4; j++) {
            int idx = t + 256 * j;
            int row = idx >> 3, kc = (idx & 7) * 4;
            float4 v = make_float4(0.f, 0.f, 0.f, 0.f);
            if (m0 + row < M)
                v = *(const float4*)&A[(size_t)(m0 + row) * K + k0 + kc];
            uint4 u = make_uint4(f2tf32(v.x), f2tf32(v.y), f2tf32(v.z), f2tf32(v.w));
            *(uint4*)&As[row * 36 + kc] = u;
        }
        if (cvtB) {
#pragma unroll
            for (int j = 0; j < 4; j++) {
                int idx = t + 256 * j;
                int kr = idx >> 5, nc = (idx & 31) * 4;
                float4 v = *(const float4*)&B[(size_t)(k0 + kr) * Nc + n0 + nc];
                uint4 u = make_uint4(f2tf32(v.x), f2tf32(v.y), f2tf32(v.z), f2tf32(v.w));
                *(uint4*)&Bs[kr * 136 + nc] = u;
            }
        } else {
#pragma unroll
            for (int j = 0; j < 4; j++) {
                int idx = t + 256 * j;
                int kr = idx >> 5, nc = (idx & 31) * 4;
                uint4 u = *(const uint4*)&Bu[(size_t)(k0 + kr) * Nc + n0 + nc];
                *(uint4*)&Bs[kr * 136 + nc] = u;
            }
        }
        __syncthreads();
#pragma unroll
        for (int ks = 0; ks < 4; ks++) {
            uint32_t af[4][4], bf[4][2];
            const int kk = ks * 8 + (lane & 3);
#pragma unroll
            for (int mt = 0; mt < 4; mt++) {
                int m = wm + mt * 16 + (lane >> 2);
                af[mt][0] = As[m * 36 + kk];
                af[mt][1] = As[(m + 8) * 36 + kk];
                af[mt][2] = As[m * 36 + kk + 4];
                af[mt][3] = As[(m + 8) * 36 + kk + 4];
            }
#pragma unroll
            for (int nt = 0; nt < 4; nt++) {
                int n = wn + nt * 8 + (lane >> 2);
                bf[nt][0] = Bs[kk * 136 + n];
                bf[nt][1] = Bs[(kk + 4) * 136 + n];
            }
#pragma unroll
            for (int mt = 0; mt < 4; mt++)
#pragma unroll
                for (int nt = 0; nt < 4; nt++) {
                    asm volatile(
                        "mma.sync.aligned.m16n8k8.row.col.f32.tf32.tf32.f32 "
                        "{%0,%1,%2,%3}, {%4,%5,%6,%7}, {%8,%9}, {%0,%1,%2,%3};\n"
                        : "+f"(acc[mt][nt][0]), "+f"(acc[mt][nt][1]),
                          "+f"(acc[mt][nt][2]), "+f"(acc[mt][nt][3])
                        : "r"(af[mt][0]), "r"(af[mt][1]), "r"(af[mt][2]), "r"(af[mt][3]),
                          "r"(bf[nt][0]), "r"(bf[nt][1]));
                }
        }
        __syncthreads();
    }
#pragma unroll
    for (int mt = 0; mt < 4; mt++) {
#pragma unroll
        for (int nt = 0; nt < 4; nt++) {
            int r = m0 + wm + mt * 16 + (lane >> 2);
            int c = n0 + wn + nt * 8 + 2 * (lane & 3);
            float b0 = bias ? bias[c] : 0.f;
            float b1 = bias ? bias[c + 1] : 0.f;
            if (r < M) {
                float2 v = make_float2(acc[mt][nt][0] + b0, acc[mt][nt][1] + b1);
                *(float2*)&C[(size_t)r * Nc + c] = v;
            }
            if (r + 8 < M) {
                float2 v = make_float2(acc[mt][nt][2] + b0, acc[mt][nt][3] + b1);
                *(float2*)&C[(size_t)(r + 8) * Nc + c] = v;
            }
        }
    }
}

// ---------------- GAT coefficients ----------------
__global__ void coef1k(const float* __restrict__ asw, const float* __restrict__ adw) {
    int w = (blockIdx.x * blockDim.x + threadIdx.x) >> 5;
    if (w >= NN) return;
    int lane = threadIdx.x & 31;
    int hd = lane >> 2;
    int l2 = lane & 3;
    const float4* hp = (const float4*)(g_h1 + (size_t)w * 384);
    const float4* ap = (const float4*)asw;
    const float4* dp = (const float4*)adw;
    float s = 0.f, d = 0.f;
#pragma unroll
    for (int i = 0; i < 3; i++) {
        int c4 = hd * 12 + l2 + 4 * i;
        float4 v = hp[c4], a = ap[c4], dd = dp[c4];
        s += v.x * a.x + v.y * a.y + v.z * a.z + v.w * a.w;
        d += v.x * dd.x + v.y * dd.y + v.z * dd.z + v.w * dd.w;
    }
    s += __shfl_xor_sync(0xffffffffu, s, 1);
    s += __shfl_xor_sync(0xffffffffu, s, 2);
    d += __shfl_xor_sync(0xffffffffu, d, 1);
    d += __shfl_xor_sync(0xffffffffu, d, 2);
    if (l2 == 0) {
        g_as1[w * 8 + hd] = s;
        g_ad1[w * 8 + hd] = d;
    }
}

__global__ void coef2k(const float* __restrict__ asw, const float* __restrict__ adw) {
    int gw = (blockIdx.x * blockDim.x + threadIdx.x) >> 5;
    if (gw >= NN) return;
    int lane = threadIdx.x & 31;
    const float* hp = g_h2 + (size_t)gw * 256;
    float s = 0.f, d = 0.f;
#pragma unroll
    for (int k = 0; k < 8; k++) {
        int c = lane + 32 * k;
        float v = hp[c];
        s += v * asw[c]; d += v * adw[c];
    }
#pragma unroll
    for (int off = 16; off; off >>= 1) {
        s += __shfl_down_sync(0xffffffffu, s, off);
        d += __shfl_down_sync(0xffffffffu, d, off);
    }
    if (lane == 0) { g_as2[gw] = s; g_ad2[gw] = d; }
}

// ---------------- CSR gather aggregation ----------------
__global__ void gath1k() {
    int w = (blockIdx.x * blockDim.x + threadIdx.x) >> 5;
    if (w >= NN) return;
    int lane = threadIdx.x & 31;
    int beg = g_off[w], end = g_off[w + 1];
    float ad = (lane < 8) ? g_ad1[w * 8 + lane] : 0.f;
    float den = 0.f;
    float4 acc[3];
#pragma unroll
    for (int i = 0; i < 3; i++) acc[i] = make_float4(0.f, 0.f, 0.f, 0.f);

    int s = g_srcl[beg];
    for (int j = beg; j < end; j++) {
        int snext = (j + 1 < end) ? g_srcl[j + 1] : 0;
        float ex = 0.f;
        if (lane < 8) {
            ex = __expf(leaky(g_as1[s * 8 + lane] + ad));
            den += ex;
        }
        const float4* hs = (const float4*)(g_h1 + (size_t)s * 384);
#pragma unroll
        for (int i = 0; i < 3; i++) {
            int c4 = lane + 32 * i;
            float a = __shfl_sync(0xffffffffu, ex, c4 / 12);
            float4 v = hs[c4];
            acc[i].x += v.x * a; acc[i].y += v.y * a;
            acc[i].z += v.z * a; acc[i].w += v.w * a;
        }
        s = snext;
    }
    float4* od = (float4*)(g_gout1 + (size_t)w * 384);
#pragma unroll
    for (int i = 0; i < 3; i++) {
        int c4 = lane + 32 * i;
        float dh = __shfl_sync(0xffffffffu, den, c4 / 12);
        float inv = 1.f / (dh + 1e-16f);
        od[c4] = make_float4(acc[i].x * inv, acc[i].y * inv, acc[i].z * inv, acc[i].w * inv);
    }
}

__global__ void gath2k() {
    int w = (blockIdx.x * blockDim.x + threadIdx.x) >> 5;
    if (w >= NN) return;
    int lane = threadIdx.x & 31;
    int beg = g_off[w], end = g_off[w + 1];
    float ad = g_ad2[w];
    float den = 0.f;
    float4 acc[2];
    acc[0] = make_float4(0.f, 0.f, 0.f, 0.f);
    acc[1] = make_float4(0.f, 0.f, 0.f, 0.f);

    int s = g_srcl[beg];
    for (int j = beg; j < end; j++) {
        int snext = (j + 1 < end) ? g_srcl[j + 1] : 0;
        float ex = __expf(leaky(g_as2[s] + ad));
        den += ex;
        const float4* hs = (const float4*)(g_h2 + (size_t)s * 256);
#pragma unroll
        for (int i = 0; i < 2; i++) {
            float4 v = hs[lane + 32 * i];
            acc[i].x += v.x * ex; acc[i].y += v.y * ex;
            acc[i].z += v.z * ex; acc[i].w += v.w * ex;
        }
        s = snext;
    }
    float inv = 1.f / (den + 1e-16f);
    float4* od = (float4*)(g_gout2 + (size_t)w * 256);
#pragma unroll
    for (int i = 0; i < 2; i++)
        od[lane + 32 * i] = make_float4(acc[i].x * inv, acc[i].y * inv,
                                        acc[i].z * inv, acc[i].w * inv);
}

// ---------------- batch norm partials + fused last-block finalize -------------
__global__ void bnpf(const float* __restrict__ X, int C,
                     float* __restrict__ psum, float* __restrict__ pss,
                     float* __restrict__ mu, float* __restrict__ rs,
                     int ctr_idx) {
    int col = blockIdx.x * 32 + threadIdx.x;
    int tt = threadIdx.y * 32 + threadIdx.x;
    float s = 0.f, q = 0.f;
    for (int r = threadIdx.y + blockIdx.y * 8; r < NN; r += 8 * gridDim.y) {
        float v = X[(size_t)r * C + col];
        s += v; q += v * v;
    }
    __shared__ float sh[8][32], sh2[8][32];
    sh[threadIdx.y][threadIdx.x] = s;
    sh2[threadIdx.y][threadIdx.x] = q;
    __syncthreads();
    if (threadIdx.y == 0) {
#pragma unroll
        for (int y = 1; y < 8; y++) { s += sh[y][threadIdx.x]; q += sh2[y][threadIdx.x]; }
        psum[blockIdx.y * C + col] = s;
        pss[blockIdx.y * C + col] = q;
    }
    __threadfence();
    __syncthreads();
    __shared__ bool isLast;
    if (tt == 0)
        isLast = (atomicAdd(&g_ctr[ctr_idx], 1) == (int)(gridDim.x * gridDim.y) - 1);
    __syncthreads();
    if (isLast) {
        __threadfence();
        for (int c = tt; c < C; c += 256) {
            float ss = 0.f, qq = 0.f;
#pragma unroll
            for (int y = 0; y < 16; y++) { ss += psum[y * C + c]; qq += pss[y * C + c]; }
            float m = ss * (1.f / NN);
            float v = qq * (1.f / NN) - m * m;
            mu[c] = m;
            rs[c] = rsqrtf(v + 1e-5f);
        }
    }
}

// hr = relu(residual + (gout - mu)*rstd*gamma + beta)
__global__ void fuse1k(const float* __restrict__ x,
                       const float* __restrict__ g, const float* __restrict__ b) {
    int idx = blockIdx.x * blockDim.x + threadIdx.x;
    if (idx >= NN * 384) return;
    int c = idx % 384;
    float val = (g_gout1[idx] - g_mu1[c]) * g_rs1[c] * g[c] + b[c];
    float h = x[idx] + val;
    g_hr1[idx] = h > 0.f ? h : 0.f;
}
__global__ void fuse2k(const float* __restrict__ g, const float* __restrict__ b) {
    int idx = blockIdx.x * blockDim.x + threadIdx.x;
    if (idx >= NN * 256) return;
    int c = idx & 255;
    float val = (g_gout2[idx] - g_mu2[c]) * g_rs2[c] * g[c] + b[c];
    float h = g_h5[idx] + val;
    g_hr2[idx] = h > 0.f ? h : 0.f;
}

// ---------------- pair head ----------------
__global__ void pairk(const int* __restrict__ ei, const int* __restrict__ tid,
                      const float* __restrict__ w4, const float* __restrict__ b4,
                      float* __restrict__ out) {
    int gw = (blockIdx.x * blockDim.x + threadIdx.x) >> 5;
    if (gw >= TEN) return;
    int lane = threadIdx.x & 31;
    int e = tid[gw];
    int s = ei[e], d = ei[EE + e];
    const float* hs = g_hf + (size_t)s * 256;
    const float* hd = g_hf + (size_t)d * 256;
    float acc[7] = {};
#pragma unroll
    for (int k = 0; k < 8; k++) {
        int c = lane + 32 * k;
        float p = hs[c] * hd[c];
        const float* wr = &w4[c * 7];
#pragma unroll
        for (int j = 0; j < 7; j++) acc[j] += p * wr[j];
    }
#pragma unroll
    for (int j = 0; j < 7; j++)
#pragma unroll
        for (int off = 16; off; off >>= 1)
            acc[j] += __shfl_down_sync(0xffffffffu, acc[j], off);
    if (lane == 0) {
#pragma unroll
        for (int j = 0; j < 7; j++) out[(size_t)gw * 7 + j] = acc[j] + b4[j];
    }
}

// ---------------- launch ----------------
extern "C" void kernel_launch(void* const* d_in, const int* in_sizes, int n_in,
                              void* d_out, int out_size) {
    const float* x       = (const float*)d_in[0];
    const int*   ei      = (const int*)d_in[1];
    const int*   teid    = (const int*)d_in[2];
    const float* fc1_w   = (const float*)d_in[3];
    const float* fc1_b   = (const float*)d_in[4];
    const float* fc5_w   = (const float*)d_in[5];
    const float* fc5_b   = (const float*)d_in[6];
    const float* fc2_w   = (const float*)d_in[7];
    const float* fc2_b   = (const float*)d_in[8];
    const float* fc4_w   = (const float*)d_in[9];
    const float* fc4_b   = (const float*)d_in[10];
    const float* gat1_w  = (const float*)d_in[11];
    const float* gat1_as = (const float*)d_in[12];
    const float* gat1_ad = (const float*)d_in[13];
    /* gat1_b unused: BN-invariant */
    const float* gat2_w  = (const float*)d_in[15];
    const float* gat2_as = (const float*)d_in[16];
    const float* gat2_ad = (const float*)d_in[17];
    /* gat2_b unused: BN-invariant */
    const float* bn1_g   = (const float*)d_in[19];
    const float* bn1_b   = (const float*)d_in[20];
    const float* bn2_g   = (const float*)d_in[21];
    const float* bn2_b   = (const float*)d_in[22];
    float* out = (float*)d_out;

    float *p_w1c, *p_b1c, *p_w5r, *p_wg2r, *p_w2r;
    float *p_h1, *p_hr1, *p_h5, *p_h2, *p_hr2, *p_hf, *p_gout1, *p_gout2;
    float *p_psum1, *p_pss1, *p_mu1, *p_rs1, *p_psum2, *p_pss2, *p_mu2, *p_rs2;
    cudaGetSymbolAddress((void**)&p_w1c, g_w1c);
    cudaGetSymbolAddress((void**)&p_b1c, g_b1c);
    cudaGetSymbolAddress((void**)&p_w5r, g_w5r);
    cudaGetSymbolAddress((void**)&p_wg2r, g_wg2r);
    cudaGetSymbolAddress((void**)&p_w2r, g_w2r);
    cudaGetSymbolAddress((void**)&p_h1, g_h1);
    cudaGetSymbolAddress((void**)&p_hr1, g_hr1);
    cudaGetSymbolAddress((void**)&p_h5, g_h5);
    cudaGetSymbolAddress((void**)&p_h2, g_h2);
    cudaGetSymbolAddress((void**)&p_hr2, g_hr2);
    cudaGetSymbolAddress((void**)&p_hf, g_hf);
    cudaGetSymbolAddress((void**)&p_gout1, g_gout1);
    cudaGetSymbolAddress((void**)&p_gout2, g_gout2);
    cudaGetSymbolAddress((void**)&p_psum1, g_psum1);
    cudaGetSymbolAddress((void**)&p_pss1, g_pss1);
    cudaGetSymbolAddress((void**)&p_mu1, g_mu1);
    cudaGetSymbolAddress((void**)&p_rs1, g_rs1);
    cudaGetSymbolAddress((void**)&p_psum2, g_psum2);
    cudaGetSymbolAddress((void**)&p_pss2, g_pss2);
    cudaGetSymbolAddress((void**)&p_mu2, g_mu2);
    cudaGetSymbolAddress((void**)&p_rs2, g_rs2);

    const int MB = (NN + 127) / 128;  // 79

    // setup: zero, then all independent prep (weight fuse/round, bias, degrees+scan)
    setupA<<<(384 * 384 + 255) / 256, 256>>>();
    setupB<<<NB_ALL, 256>>>(fc1_w, gat1_w, fc1_b, fc5_w, gat2_w, fc2_w, ei);
    fillk<<<(EA + 255) / 256, 256>>>(ei);

    // h1 = x @ w1c + b1c (in-kernel B cvt; w1c is raw fp32)
    gemm_tf32<<<dim3(3, MB), 256>>>(x, p_w1c, p_b1c, p_h1, NN, 384, 384, 1);

    coef1k<<<(NN * 32 + 255) / 256, 256>>>(gat1_as, gat1_ad);
    gath1k<<<(NN * 32 + 255) / 256, 256>>>();

    bnpf<<<dim3(12, 16), dim3(32, 8)>>>(p_gout1, 384, p_psum1, p_pss1, p_mu1, p_rs1, 1);
    fuse1k<<<(NN * 384 + 255) / 256, 256>>>(x, bn1_g, bn1_b);

    gemm_tf32<<<dim3(2, MB), 256>>>(p_hr1, p_w5r, fc5_b, p_h5, NN, 384, 256, 0);
    gemm_tf32<<<dim3(2, MB), 256>>>(p_h5, p_wg2r, nullptr, p_h2, NN, 256, 256, 0);

    coef2k<<<(NN * 32 + 255) / 256, 256>>>(gat2_as, gat2_ad);
    gath2k<<<(NN * 32 + 255) / 256, 256>>>();

    bnpf<<<dim3(8, 16), dim3(32, 8)>>>(p_gout2, 256, p_psum2, p_pss2, p_mu2, p_rs2, 2);
    fuse2k<<<(NN * 256 + 255) / 256, 256>>>(bn2_g, bn2_b);

    gemm_tf32<<<dim3(2, MB), 256>>>(p_hr2, p_w2r, fc2_b, p_hf, NN, 256, 256, 0);

    pairk<<<(TEN * 32 + 255) / 256, 256>>>(ei, teid, fc4_w, fc4_b, out);
}